// round 6
// baseline (speedup 1.0000x reference)
#include <cuda_runtime.h>
#include <math.h>

// ---------------------------------------------------------------------------
// VQ-VAE forward, fp32. Packed f32x2 FMA inner loops, BN fused into consumers.
// ---------------------------------------------------------------------------

#define BB 64
static const float BN_EPS = 1e-5f;

// ------------------------- scratch (device globals) ------------------------
__device__ float g_a1[64 * 16 * 128 * 128];
__device__ float g_a2[64 * 32 * 64 * 64];
__device__ float g_a3[64 * 64 * 32 * 32];
__device__ float g_q [64 * 64 * 32 * 32];
__device__ float g_d1[64 * 32 * 64 * 64];
__device__ float g_d2[64 * 16 * 128 * 128];

__device__ int    g_idx[65536];
__device__ float  g_codeNorm[512];
__device__ float2 g_part[64 * 32];
__device__ float  g_bnSc[6 * 64];
__device__ float  g_bnSh[6 * 64];
__device__ float  g_lossPart[512];

// ---------------------------- f32x2 helpers --------------------------------
__device__ __forceinline__ unsigned long long splat2(float v) {
    unsigned long long r;
    asm("mov.b64 %0, {%1, %1};" : "=l"(r) : "r"(__float_as_uint(v)));
    return r;
}
__device__ __forceinline__ unsigned long long pack2(float a, float b) {
    unsigned long long r;
    asm("mov.b64 %0, {%1, %2};" : "=l"(r)
        : "r"(__float_as_uint(a)), "r"(__float_as_uint(b)));
    return r;
}
__device__ __forceinline__ void unpack2(unsigned long long p, float& a, float& b) {
    unsigned int lo, hi;
    asm("mov.b64 {%0, %1}, %2;" : "=r"(lo), "=r"(hi) : "l"(p));
    a = __uint_as_float(lo); b = __uint_as_float(hi);
}
__device__ __forceinline__ void fma2(unsigned long long& acc,
                                     unsigned long long a, unsigned long long b) {
    asm("fma.rn.f32x2 %0, %1, %2, %0;" : "+l"(acc) : "l"(a), "l"(b));
}

// ------------------------------ conv k4 s2 p1 ------------------------------
// Block = 16x16 output tile. Optional fused BN+ReLU applied to input on load.
template <int CIN, int COUT, int COUTG, int CICHUNK, int HIN, int WIN, bool FUSE>
__global__ __launch_bounds__(256)
void conv_t(const float* __restrict__ in, const float* __restrict__ w,
            const float* __restrict__ bias, float* __restrict__ out,
            const float* __restrict__ bnsc, const float* __restrict__ bnsh)
{
    constexpr int HOUT = HIN / 2, WOUT = WIN / 2;
    constexpr int NBX = WOUT / 16, NBY = HOUT / 16;
    constexpr int TIN = 34, TP = 36;

    __shared__ float tile[CICHUNK][TIN][TP];
    __shared__ __align__(16) float ws[CICHUNK * 16 * COUTG];

    const int b  = blockIdx.x;
    const int tx = b % NBX;
    const int ty = (b / NBX) % NBY;
    const int n  = b / (NBX * NBY);
    const int cog = blockIdx.y * COUTG;
    const int lx = threadIdx.x & 15, ly = threadIdx.x >> 4;

    const int X0 = tx * 32 - 1, Y0 = ty * 32 - 1;
    const float* inn = in + (long long)n * CIN * HIN * WIN;

    unsigned long long acc2[COUTG / 2];
    #pragma unroll
    for (int j = 0; j < COUTG / 2; j++)
        acc2[j] = pack2(__ldg(&bias[cog + 2 * j]), __ldg(&bias[cog + 2 * j + 1]));

    for (int ci0 = 0; ci0 < CIN; ci0 += CICHUNK) {
        __syncthreads();
        for (int t = threadIdx.x; t < COUTG * CICHUNK * 16; t += 256) {
            const int j  = t % COUTG;
            const int kk = t / COUTG;
            ws[t] = w[(cog + j) * CIN * 16 + ci0 * 16 + kk];
        }
        for (int t = threadIdx.x; t < CICHUNK * TIN * 34; t += 256) {
            const int c  = t / (TIN * 34);
            const int r  = (t / 34) % TIN;
            const int cc = t % 34;
            const int gy = Y0 + r, gx = X0 + cc;
            const bool ok = ((unsigned)gy < (unsigned)HIN) &&
                            ((unsigned)gx < (unsigned)WIN);
            float v = ok ?
                __ldg(&inn[((long long)(ci0 + c) * HIN + gy) * WIN + gx]) : 0.f;
            if (FUSE && ok)
                v = fmaxf(0.f, fmaf(v, bnsc[ci0 + c], bnsh[ci0 + c]));
            tile[c][r][cc] = v;
        }
        __syncthreads();

        #pragma unroll
        for (int cil = 0; cil < CICHUNK; cil++) {
            float tap[16];
            #pragma unroll
            for (int ky = 0; ky < 4; ky++)
                #pragma unroll
                for (int kx = 0; kx < 4; kx++)
                    tap[ky * 4 + kx] = tile[cil][2 * ly + ky][2 * lx + kx];
            #pragma unroll
            for (int k = 0; k < 16; k++) {
                const unsigned long long t2 = splat2(tap[k]);
                const ulonglong2* w8 =
                    (const ulonglong2*)&ws[(cil * 16 + k) * COUTG];
                #pragma unroll
                for (int j4 = 0; j4 < COUTG / 4; j4++) {
                    const ulonglong2 wp = w8[j4];
                    fma2(acc2[2 * j4 + 0], t2, wp.x);
                    fma2(acc2[2 * j4 + 1], t2, wp.y);
                }
            }
        }
    }

    const int oy = ty * 16 + ly, ox = tx * 16 + lx;
    #pragma unroll
    for (int j = 0; j < COUTG / 2; j++) {
        float v0, v1; unpack2(acc2[j], v0, v1);
        out[(((long long)n * COUT + cog + 2*j)   * HOUT + oy) * WOUT + ox] = v0;
        out[(((long long)n * COUT + cog + 2*j+1) * HOUT + oy) * WOUT + ox] = v1;
    }
}

// --------------------------- deconv k4 s2 p1 -------------------------------
template <int CIN, int COUT, int COUTG, int COUTG_PAD, int CICHUNK,
          int HIN, int WIN, bool FUSE>
__global__ __launch_bounds__(256)
void deconv_t(const float* __restrict__ in, const float* __restrict__ w,
              const float* __restrict__ bias, float* __restrict__ out,
              const float* __restrict__ bnsc, const float* __restrict__ bnsh)
{
    constexpr int HOUT = HIN * 2, WOUT = WIN * 2;
    constexpr int NBX = WIN / 16, NBY = HIN / 16;
    constexpr int TIN = 18, TP = 20;

    __shared__ float tile[CICHUNK][TIN][TP];
    __shared__ __align__(16) float ws[CICHUNK * 16 * COUTG_PAD];

    const int b  = blockIdx.x;
    const int tx = b % NBX;
    const int ty = (b / NBX) % NBY;
    const int n  = b / (NBX * NBY);
    const int cog = blockIdx.y * COUTG;
    const int lx = threadIdx.x & 15, ly = threadIdx.x >> 4;

    const int X0 = tx * 16 - 1, Y0 = ty * 16 - 1;
    const float* inn = in + (long long)n * CIN * HIN * WIN;

    unsigned long long acc2[4][COUTG_PAD / 2];
    #pragma unroll
    for (int j = 0; j < COUTG_PAD / 2; j++) {
        const float b0 = (cog + 2*j   < COUT) ? __ldg(&bias[cog + 2*j])   : 0.f;
        const float b1 = (cog + 2*j+1 < COUT) ? __ldg(&bias[cog + 2*j+1]) : 0.f;
        const unsigned long long bp = pack2(b0, b1);
        acc2[0][j] = bp; acc2[1][j] = bp; acc2[2][j] = bp; acc2[3][j] = bp;
    }

    for (int ci0 = 0; ci0 < CIN; ci0 += CICHUNK) {
        __syncthreads();
        for (int t = threadIdx.x; t < COUTG_PAD * CICHUNK * 16; t += 256) {
            const int j  = t % COUTG_PAD;
            const int kk = t / COUTG_PAD;
            ws[t] = (cog + j < COUT) ? w[(cog + j) * CIN * 16 + ci0 * 16 + kk] : 0.f;
        }
        for (int t = threadIdx.x; t < CICHUNK * TIN * TIN; t += 256) {
            const int c  = t / (TIN * TIN);
            const int r  = (t / TIN) % TIN;
            const int cc = t % TIN;
            const int gy = Y0 + r, gx = X0 + cc;
            const bool ok = ((unsigned)gy < (unsigned)HIN) &&
                            ((unsigned)gx < (unsigned)WIN);
            float v = ok ?
                __ldg(&inn[((long long)(ci0 + c) * HIN + gy) * WIN + gx]) : 0.f;
            if (FUSE && ok)
                v = fmaxf(0.f, fmaf(v, bnsc[ci0 + c], bnsh[ci0 + c]));
            tile[c][r][cc] = v;
        }
        __syncthreads();

        #pragma unroll
        for (int cil = 0; cil < CICHUNK; cil++) {
            float tv[3][3];
            #pragma unroll
            for (int r = 0; r < 3; r++)
                #pragma unroll
                for (int c = 0; c < 3; c++)
                    tv[r][c] = tile[cil][ly + r][lx + c];
            #pragma unroll
            for (int ky = 0; ky < 4; ky++) {
                #pragma unroll
                for (int kx = 0; kx < 4; kx++) {
                    const int py = ky & 1, px = kx & 1;
                    const unsigned long long t2 =
                        splat2(tv[(ky >> 1) + py][(kx >> 1) + px]);
                    const int o = py * 2 + px;
                    const ulonglong2* w8 =
                        (const ulonglong2*)&ws[(cil * 16 + ky * 4 + kx) * COUTG_PAD];
                    #pragma unroll
                    for (int j4 = 0; j4 < COUTG_PAD / 4; j4++) {
                        const ulonglong2 wp = w8[j4];
                        fma2(acc2[o][2 * j4 + 0], t2, wp.x);
                        fma2(acc2[o][2 * j4 + 1], t2, wp.y);
                    }
                }
            }
        }
    }

    const int Y = ty * 16 + ly, X = tx * 16 + lx;
    #pragma unroll
    for (int j = 0; j < COUTG; j++) {
        float v[4];
        {
            float a, bqq; unpack2(acc2[0][j >> 1], a, bqq);
            v[0] = (j & 1) ? bqq : a;
        }
        {
            float a, bqq; unpack2(acc2[1][j >> 1], a, bqq);
            v[1] = (j & 1) ? bqq : a;
        }
        {
            float a, bqq; unpack2(acc2[2][j >> 1], a, bqq);
            v[2] = (j & 1) ? bqq : a;
        }
        {
            float a, bqq; unpack2(acc2[3][j >> 1], a, bqq);
            v[3] = (j & 1) ? bqq : a;
        }
        const long long cb = (long long)n * COUT + cog + j;
        float2* row0 = (float2*)out + (cb * HOUT + 2 * Y) * (WOUT / 2) + X;
        float2* row1 = (float2*)out + (cb * HOUT + 2 * Y + 1) * (WOUT / 2) + X;
        *row0 = make_float2(v[0], v[1]);
        *row1 = make_float2(v[2], v[3]);
    }
}

// ------------------------------- batchnorm ---------------------------------
__global__ __launch_bounds__(256)
void bn_stats(const float* __restrict__ x, int C, int HW)
{
    const int c = blockIdx.x >> 5;
    const int s = blockIdx.x & 31;
    const int chunk4 = HW >> 7;

    float sum = 0.f, sq = 0.f;
    for (int n = 0; n < BB; n++) {
        const float4* base = (const float4*)(x + ((long long)(n * C + c)) * HW) +
                             s * chunk4;
        for (int p = threadIdx.x; p < chunk4; p += 256) {
            float4 v = base[p];
            sum += v.x + v.y + v.z + v.w;
            sq = fmaf(v.x, v.x, sq); sq = fmaf(v.y, v.y, sq);
            sq = fmaf(v.z, v.z, sq); sq = fmaf(v.w, v.w, sq);
        }
    }
    __shared__ float s1[256], s2[256];
    s1[threadIdx.x] = sum; s2[threadIdx.x] = sq;
    __syncthreads();
    for (int off = 128; off; off >>= 1) {
        if (threadIdx.x < off) {
            s1[threadIdx.x] += s1[threadIdx.x + off];
            s2[threadIdx.x] += s2[threadIdx.x + off];
        }
        __syncthreads();
    }
    if (threadIdx.x == 0) g_part[blockIdx.x] = make_float2(s1[0], s2[0]);
}

__global__ void bn_finalize(const float* __restrict__ gam,
                            const float* __restrict__ bet, int HW,
                            float* __restrict__ outSc, float* __restrict__ outSh)
{
    const int c = blockIdx.x;
    float2 p = g_part[c * 32 + threadIdx.x];
    double S = p.x, Q = p.y;
    for (int off = 16; off; off >>= 1) {
        S += __shfl_down_sync(0xffffffffu, S, off);
        Q += __shfl_down_sync(0xffffffffu, Q, off);
    }
    if (threadIdx.x == 0) {
        const double P = (double)BB * (double)HW;
        const double mean = S / P;
        const double var  = Q / P - mean * mean;
        const float rstd  = (float)(1.0 / sqrt(var + (double)BN_EPS));
        const float sc = gam[c] * rstd;
        outSc[c] = sc;
        outSh[c] = bet[c] - (float)mean * sc;
    }
}

// final tanh pass only
__global__ __launch_bounds__(256)
void bn_apply_tanh(float* __restrict__ x, int C, int HW, int total4,
                   const float* __restrict__ sc_, const float* __restrict__ sh_)
{
    const int i = blockIdx.x * 256 + threadIdx.x;
    if (i >= total4) return;
    const int hw4 = HW >> 2;
    const int c = (i / hw4) % C;
    const float sc = sc_[c], sh = sh_[c];
    float4 v = ((float4*)x)[i];
    v.x = tanhf(fmaf(v.x, sc, sh)); v.y = tanhf(fmaf(v.y, sc, sh));
    v.z = tanhf(fmaf(v.z, sc, sh)); v.w = tanhf(fmaf(v.w, sc, sh));
    ((float4*)x)[i] = v;
}

// ---------------------------------- VQ -------------------------------------
__global__ void code_norms(const float* __restrict__ cb)
{
    const int k = threadIdx.x;
    float s = 0.f;
    const float* r = cb + k * 64;
    #pragma unroll
    for (int d = 0; d < 64; d++) s = fmaf(r[d], r[d], s);
    g_codeNorm[k] = s;
}

// BN+ReLU of z_e fused into the load (sc/sh slot of encoder layer 3).
__global__ __launch_bounds__(128)
void vq_argmin(const float* __restrict__ ze, const float* __restrict__ cb,
               const float* __restrict__ sc_, const float* __restrict__ sh_)
{
    __shared__ float sc[64 * 64];
    __shared__ float scn[64];
    __shared__ float red[128];
    __shared__ float ssc[64], ssh[64];

    if (threadIdx.x < 64) {
        ssc[threadIdx.x] = sc_[threadIdx.x];
        ssh[threadIdx.x] = sh_[threadIdx.x];
    }
    __syncthreads();

    const int idx = blockIdx.x * 128 + threadIdx.x;
    const int n  = idx >> 10;
    const int hw = idx & 1023;
    const float* base = ze + (long long)n * 64 * 1024 + hw;

    float z[64];
    #pragma unroll
    for (int d = 0; d < 64; d++)
        z[d] = fmaxf(0.f, fmaf(base[d * 1024], ssc[d], ssh[d]));
    float zz = 0.f;
    #pragma unroll
    for (int d = 0; d < 64; d++) zz = fmaf(z[d], z[d], zz);

    float best = 3.4e38f;
    int   bi   = 0;
    for (int ch = 0; ch < 8; ch++) {
        __syncthreads();
        for (int t = threadIdx.x; t < 1024; t += 128)
            ((float4*)sc)[t] = ((const float4*)(cb + ch * 4096))[t];
        if (threadIdx.x < 64) scn[threadIdx.x] = g_codeNorm[ch * 64 + threadIdx.x];
        __syncthreads();
        #pragma unroll 2
        for (int j = 0; j < 64; j++) {
            const float4* cp = (const float4*)&sc[j * 64];
            float dot = 0.f;
            #pragma unroll
            for (int d4 = 0; d4 < 16; d4++) {
                float4 c4 = cp[d4];
                dot = fmaf(z[4*d4+0], c4.x, dot);
                dot = fmaf(z[4*d4+1], c4.y, dot);
                dot = fmaf(z[4*d4+2], c4.z, dot);
                dot = fmaf(z[4*d4+3], c4.w, dot);
            }
            const float dist = zz - 2.f * dot + scn[j];
            const int k = ch * 64 + j;
            if (dist < best) { best = dist; bi = k; }
        }
    }
    g_idx[idx] = bi;

    const float* cr = cb + bi * 64;
    float e = 0.f;
    #pragma unroll
    for (int d = 0; d < 64; d++) { float df = z[d] - cr[d]; e = fmaf(df, df, e); }

    red[threadIdx.x] = e;
    __syncthreads();
    for (int off = 64; off; off >>= 1) {
        if (threadIdx.x < off) red[threadIdx.x] += red[threadIdx.x + off];
        __syncthreads();
    }
    if (threadIdx.x == 0) g_lossPart[blockIdx.x] = red[0];
}

__global__ void vq_loss_final(float* __restrict__ loss_out)
{
    __shared__ double red[512];
    red[threadIdx.x] = (double)g_lossPart[threadIdx.x];
    __syncthreads();
    for (int off = 256; off; off >>= 1) {
        if (threadIdx.x < off) red[threadIdx.x] += red[threadIdx.x + off];
        __syncthreads();
    }
    if (threadIdx.x == 0)
        loss_out[0] = (float)(2.0 * red[0] / (65536.0 * 64.0));
}

__global__ __launch_bounds__(256)
void vq_scatter(float* __restrict__ q, const float* __restrict__ cb)
{
    const int i = blockIdx.x * 256 + threadIdx.x;
    const int hw = i & 1023;
    const int d  = (i >> 10) & 63;
    const int n  = i >> 16;
    const int code = g_idx[n * 1024 + hw];
    q[i] = cb[code * 64 + d];
}

// -------------------------------- launch -----------------------------------
static inline int nblk(long long total) { return (int)((total + 255) / 256); }

extern "C" void kernel_launch(void* const* d_in, const int* in_sizes, int n_in,
                              void* d_out, int out_size)
{
    (void)in_sizes; (void)n_in;
    const float* x    = (const float*)d_in[0];
    const float* cb   = (const float*)d_in[1];
    const float* eW1  = (const float*)d_in[2];
    const float* eb1  = (const float*)d_in[3];
    const float* eg1  = (const float*)d_in[4];
    const float* ebt1 = (const float*)d_in[5];
    const float* eW2  = (const float*)d_in[6];
    const float* eb2  = (const float*)d_in[7];
    const float* eg2  = (const float*)d_in[8];
    const float* ebt2 = (const float*)d_in[9];
    const float* eW3  = (const float*)d_in[10];
    const float* eb3  = (const float*)d_in[11];
    const float* eg3  = (const float*)d_in[12];
    const float* ebt3 = (const float*)d_in[13];
    const float* dW1  = (const float*)d_in[14];
    const float* db1  = (const float*)d_in[15];
    const float* dg1  = (const float*)d_in[16];
    const float* dbt1 = (const float*)d_in[17];
    const float* dW2  = (const float*)d_in[18];
    const float* db2  = (const float*)d_in[19];
    const float* dg2  = (const float*)d_in[20];
    const float* dbt2 = (const float*)d_in[21];
    const float* dW3  = (const float*)d_in[22];
    const float* db3  = (const float*)d_in[23];
    const float* dg3  = (const float*)d_in[24];
    const float* dbt3 = (const float*)d_in[25];
    float* out = (float*)d_out;

    float *a1, *a2, *a3, *q, *d1, *d2, *bnSc, *bnSh;
    cudaGetSymbolAddress((void**)&a1, g_a1);
    cudaGetSymbolAddress((void**)&a2, g_a2);
    cudaGetSymbolAddress((void**)&a3, g_a3);
    cudaGetSymbolAddress((void**)&q,  g_q);
    cudaGetSymbolAddress((void**)&d1, g_d1);
    cudaGetSymbolAddress((void**)&d2, g_d2);
    cudaGetSymbolAddress((void**)&bnSc, g_bnSc);
    cudaGetSymbolAddress((void**)&bnSh, g_bnSh);
    #define SLOT(i) (bnSc + (i) * 64), (bnSh + (i) * 64)

    // ---------------- encoder ----------------
    // conv1: 3->16 (no fuse)
    conv_t<3, 16, 16, 3, 256, 256, false><<<dim3(4096, 1), 256>>>(
        x, eW1, eb1, a1, nullptr, nullptr);
    bn_stats<<<16 * 32, 256>>>(a1, 16, 128 * 128);
    bn_finalize<<<16, 32>>>(eg1, ebt1, 128 * 128, SLOT(0));

    // conv2: 16->32, fuse BN0
    conv_t<16, 32, 32, 4, 128, 128, true><<<dim3(1024, 1), 256>>>(
        a1, eW2, eb2, a2, SLOT(0));
    bn_stats<<<32 * 32, 256>>>(a2, 32, 64 * 64);
    bn_finalize<<<32, 32>>>(eg2, ebt2, 64 * 64, SLOT(1));

    // conv3: 32->64, fuse BN1
    conv_t<32, 64, 32, 4, 64, 64, true><<<dim3(256, 2), 256>>>(
        a2, eW3, eb3, a3, SLOT(1));
    bn_stats<<<64 * 32, 256>>>(a3, 64, 32 * 32);
    bn_finalize<<<64, 32>>>(eg3, ebt3, 32 * 32, SLOT(2));

    // ---------------- vector quantization (fuse BN2 into load) -------------
    code_norms<<<1, 512>>>(cb);
    vq_argmin<<<512, 128>>>(a3, cb, SLOT(2));
    vq_loss_final<<<1, 512>>>(out + (out_size - 1));
    vq_scatter<<<nblk((long long)BB * 64 * 32 * 32), 256>>>(q, cb);

    // ---------------- decoder ----------------
    // deconv1: 64->32 (no fuse; q is raw codebook values)
    deconv_t<64, 32, 16, 16, 8, 32, 32, false><<<dim3(256, 2), 256>>>(
        q, dW1, db1, d1, nullptr, nullptr);
    bn_stats<<<32 * 32, 256>>>(d1, 32, 64 * 64);
    bn_finalize<<<32, 32>>>(dg1, dbt1, 64 * 64, SLOT(3));

    // deconv2: 32->16, fuse BN3
    deconv_t<32, 16, 16, 16, 8, 64, 64, true><<<dim3(1024, 1), 256>>>(
        d1, dW2, db2, d2, SLOT(3));
    bn_stats<<<16 * 32, 256>>>(d2, 16, 128 * 128);
    bn_finalize<<<16, 32>>>(dg2, dbt2, 128 * 128, SLOT(4));

    // deconv3: 16->3 (pad 4), fuse BN4; write raw to out, then BN+tanh
    deconv_t<16, 3, 3, 4, 16, 128, 128, true><<<dim3(4096, 1), 256>>>(
        d2, dW3, db3, out, SLOT(4));
    {
        const long long T = (long long)BB * 3 * 256 * 256;
        bn_stats<<<3 * 32, 256>>>(out, 3, 256 * 256);
        bn_finalize<<<3, 32>>>(dg3, dbt3, 256 * 256, SLOT(5));
        bn_apply_tanh<<<nblk(T / 4), 256>>>(out, 3, 256 * 256, (int)(T / 4), SLOT(5));
    }
    #undef SLOT
}

// round 7
// speedup vs baseline: 1.0888x; 1.0888x over previous
#include <cuda_runtime.h>
#include <math.h>

// ---------------------------------------------------------------------------
// VQ-VAE forward, fp32. Conv: 2x2 pixel blocks/thread. Deconv: parity-split
// threads with 2x2 quad groups. f32x2 packed FMA. BN fused into consumers.
// ---------------------------------------------------------------------------

#define BB 64
static const float BN_EPS = 1e-5f;

// ------------------------- scratch (device globals) ------------------------
__device__ float g_a1[64 * 16 * 128 * 128];
__device__ float g_a2[64 * 32 * 64 * 64];
__device__ float g_a3[64 * 64 * 32 * 32];
__device__ float g_q [64 * 64 * 32 * 32];
__device__ float g_d1[64 * 32 * 64 * 64];
__device__ float g_d2[64 * 16 * 128 * 128];

__device__ int    g_idx[65536];
__device__ float  g_codeNorm[512];
__device__ float2 g_part[64 * 32];
__device__ float  g_bnSc[6 * 64];
__device__ float  g_bnSh[6 * 64];
__device__ float  g_lossPart[512];

// ---------------------------- f32x2 helpers --------------------------------
__device__ __forceinline__ unsigned long long splat2(float v) {
    unsigned long long r;
    asm("mov.b64 %0, {%1, %1};" : "=l"(r) : "r"(__float_as_uint(v)));
    return r;
}
__device__ __forceinline__ unsigned long long pack2(float a, float b) {
    unsigned long long r;
    asm("mov.b64 %0, {%1, %2};" : "=l"(r)
        : "r"(__float_as_uint(a)), "r"(__float_as_uint(b)));
    return r;
}
__device__ __forceinline__ void unpack2(unsigned long long p, float& a, float& b) {
    unsigned int lo, hi;
    asm("mov.b64 {%0, %1}, %2;" : "=r"(lo), "=r"(hi) : "l"(p));
    a = __uint_as_float(lo); b = __uint_as_float(hi);
}
__device__ __forceinline__ void fma2(unsigned long long& acc,
                                     unsigned long long a, unsigned long long b) {
    asm("fma.rn.f32x2 %0, %1, %2, %0;" : "+l"(acc) : "l"(a), "l"(b));
}

// ------------------------------ conv k4 s2 p1 ------------------------------
// Block = 32x32 output tile; thread = 2x2 output pixels x COUTG(=16) channels.
// Input patch 66x66 per ci staged in smem; taps read as float4+float2 rows.
template <int CIN, int COUT, int COUTG, int CICHUNK, int HIN, int WIN, bool FUSE>
__global__ __launch_bounds__(256)
void conv_q(const float* __restrict__ in, const float* __restrict__ w,
            const float* __restrict__ bias, float* __restrict__ out,
            const float* __restrict__ bnsc, const float* __restrict__ bnsh)
{
    constexpr int HOUT = HIN / 2, WOUT = WIN / 2;
    constexpr int NBX = WOUT / 32, NBY = HOUT / 32;
    constexpr int TIN = 66, TP = 68;

    __shared__ __align__(16) float tile[CICHUNK][TIN][TP];
    __shared__ __align__(16) float ws[CICHUNK * 16 * COUTG];

    const int b  = blockIdx.x;
    const int tx = b % NBX;
    const int ty = (b / NBX) % NBY;
    const int n  = b / (NBX * NBY);
    const int cog = blockIdx.y * COUTG;
    const int gx = threadIdx.x & 15, gy = threadIdx.x >> 4;

    const int X0 = tx * 64 - 1, Y0 = ty * 64 - 1;
    const float* inn = in + (long long)n * CIN * HIN * WIN;

    unsigned long long acc[4][COUTG / 2];
    #pragma unroll
    for (int j = 0; j < COUTG / 2; j++) {
        const unsigned long long bp =
            pack2(__ldg(&bias[cog + 2 * j]), __ldg(&bias[cog + 2 * j + 1]));
        acc[0][j] = bp; acc[1][j] = bp; acc[2][j] = bp; acc[3][j] = bp;
    }

    for (int ci0 = 0; ci0 < CIN; ci0 += CICHUNK) {
        __syncthreads();
        for (int t = threadIdx.x; t < COUTG * CICHUNK * 16; t += 256) {
            const int j  = t % COUTG;
            const int kk = t / COUTG;
            ws[t] = w[(cog + j) * CIN * 16 + ci0 * 16 + kk];
        }
        for (int t = threadIdx.x; t < CICHUNK * TIN * TIN; t += 256) {
            const int c  = t / (TIN * TIN);
            const int r  = (t / TIN) % TIN;
            const int cc = t % TIN;
            const int gyy = Y0 + r, gxx = X0 + cc;
            const bool ok = ((unsigned)gyy < (unsigned)HIN) &&
                            ((unsigned)gxx < (unsigned)WIN);
            float v = ok ?
                __ldg(&inn[((long long)(ci0 + c) * HIN + gyy) * WIN + gxx]) : 0.f;
            if (FUSE && ok)
                v = fmaxf(0.f, fmaf(v, bnsc[ci0 + c], bnsh[ci0 + c]));
            tile[c][r][cc] = v;
        }
        __syncthreads();

        #pragma unroll
        for (int cil = 0; cil < CICHUNK; cil++) {
            float tp[6][6];
            #pragma unroll
            for (int r = 0; r < 6; r++) {
                const float4 a4 = *(const float4*)&tile[cil][4 * gy + r][4 * gx];
                const float2 a2 = *(const float2*)&tile[cil][4 * gy + r][4 * gx + 4];
                tp[r][0] = a4.x; tp[r][1] = a4.y; tp[r][2] = a4.z;
                tp[r][3] = a4.w; tp[r][4] = a2.x; tp[r][5] = a2.y;
            }
            #pragma unroll
            for (int ky = 0; ky < 4; ky++) {
                #pragma unroll
                for (int kx = 0; kx < 4; kx++) {
                    const ulonglong2* w8 =
                        (const ulonglong2*)&ws[(cil * 16 + ky * 4 + kx) * COUTG];
                    ulonglong2 wv[COUTG / 4];
                    #pragma unroll
                    for (int q = 0; q < COUTG / 4; q++) wv[q] = w8[q];
                    #pragma unroll
                    for (int iy = 0; iy < 2; iy++) {
                        #pragma unroll
                        for (int ix = 0; ix < 2; ix++) {
                            const unsigned long long t2 =
                                splat2(tp[2 * iy + ky][2 * ix + kx]);
                            #pragma unroll
                            for (int q = 0; q < COUTG / 4; q++) {
                                fma2(acc[iy * 2 + ix][2 * q + 0], t2, wv[q].x);
                                fma2(acc[iy * 2 + ix][2 * q + 1], t2, wv[q].y);
                            }
                        }
                    }
                }
            }
        }
    }

    const int oy = ty * 32 + 2 * gy, ox = tx * 32 + 2 * gx;
    #pragma unroll
    for (int j = 0; j < COUTG; j++) {
        float v00, v01, v10, v11, tA, tB;
        unpack2(acc[0][j >> 1], tA, tB); v00 = (j & 1) ? tB : tA;
        unpack2(acc[1][j >> 1], tA, tB); v01 = (j & 1) ? tB : tA;
        unpack2(acc[2][j >> 1], tA, tB); v10 = (j & 1) ? tB : tA;
        unpack2(acc[3][j >> 1], tA, tB); v11 = (j & 1) ? tB : tA;
        const long long cb = (long long)n * COUT + cog + j;
        *(float2*)&out[(cb * HOUT + oy) * WOUT + ox]     = make_float2(v00, v01);
        *(float2*)&out[(cb * HOUT + oy + 1) * WOUT + ox] = make_float2(v10, v11);
    }
}

// --------------------------- deconv k4 s2 p1 -------------------------------
// Block = 16x16 quad tile (32x32 outputs). Thread = one parity (py,px) of a
// 2x2 quad group (4 output pixels) x COUTG channels.
// Output (2Y+py, 2X+px): tap rows Y-1+py+a (a=0,1) pair with weight ky=py+2a.
template <int CIN, int COUT, int COUTG, int CICHUNK, int HIN, int WIN, bool FUSE>
__global__ __launch_bounds__(256)
void deconv_q(const float* __restrict__ in, const float* __restrict__ w,
              const float* __restrict__ bias, float* __restrict__ out,
              const float* __restrict__ bnsc, const float* __restrict__ bnsh)
{
    constexpr int HOUT = HIN * 2, WOUT = WIN * 2;
    constexpr int NBX = WIN / 16, NBY = HIN / 16;
    constexpr int TIN = 18, TP = 20;

    __shared__ float tile[CICHUNK][TIN][TP];
    __shared__ __align__(16) float ws[CICHUNK * 16 * COUTG];

    const int b  = blockIdx.x;
    const int tx = b % NBX;
    const int ty = (b / NBX) % NBY;
    const int n  = b / (NBX * NBY);
    const int cog = blockIdx.y * COUTG;

    const int px  = threadIdx.x & 1;
    const int py  = (threadIdx.x >> 1) & 1;
    const int g   = threadIdx.x >> 2;          // 0..63
    const int ggx = g & 7, ggy = g >> 3;       // 2x2 quad group coords

    const float* inn = in + (long long)n * CIN * HIN * WIN;

    unsigned long long acc[4][COUTG / 2];
    #pragma unroll
    for (int j = 0; j < COUTG / 2; j++) {
        const float b0 = (cog + 2*j   < COUT) ? __ldg(&bias[cog + 2*j])   : 0.f;
        const float b1 = (cog + 2*j+1 < COUT) ? __ldg(&bias[cog + 2*j+1]) : 0.f;
        const unsigned long long bp = pack2(b0, b1);
        acc[0][j] = bp; acc[1][j] = bp; acc[2][j] = bp; acc[3][j] = bp;
    }

    const int X0 = tx * 16 - 1, Y0 = ty * 16 - 1;

    for (int ci0 = 0; ci0 < CIN; ci0 += CICHUNK) {
        __syncthreads();
        for (int t = threadIdx.x; t < COUTG * CICHUNK * 16; t += 256) {
            const int j  = t % COUTG;
            const int kk = t / COUTG;
            ws[t] = (cog + j < COUT) ? w[(cog + j) * CIN * 16 + ci0 * 16 + kk] : 0.f;
        }
        for (int t = threadIdx.x; t < CICHUNK * TIN * TIN; t += 256) {
            const int c  = t / (TIN * TIN);
            const int r  = (t / TIN) % TIN;
            const int cc = t % TIN;
            const int gyy = Y0 + r, gxx = X0 + cc;
            const bool ok = ((unsigned)gyy < (unsigned)HIN) &&
                            ((unsigned)gxx < (unsigned)WIN);
            float v = ok ?
                __ldg(&inn[((long long)(ci0 + c) * HIN + gyy) * WIN + gxx]) : 0.f;
            if (FUSE && ok)
                v = fmaxf(0.f, fmaf(v, bnsc[ci0 + c], bnsh[ci0 + c]));
            tile[c][r][cc] = v;
        }
        __syncthreads();

        #pragma unroll
        for (int cil = 0; cil < CICHUNK; cil++) {
            // taps for this parity: rows 2ggy+py+{0..2}, cols 2ggx+px+{0..2}
            float tp[3][3];
            #pragma unroll
            for (int r = 0; r < 3; r++)
                #pragma unroll
                for (int c = 0; c < 3; c++)
                    tp[r][c] = tile[cil][2 * ggy + py + r][2 * ggx + px + c];

            #pragma unroll
            for (int a = 0; a < 2; a++) {
                #pragma unroll
                for (int bb2 = 0; bb2 < 2; bb2++) {
                    const int k = (py + 2 * a) * 4 + (px + 2 * bb2);
                    const ulonglong2* w8 =
                        (const ulonglong2*)&ws[(cil * 16 + k) * COUTG];
                    ulonglong2 wv[COUTG / 4];
                    #pragma unroll
                    for (int q = 0; q < COUTG / 4; q++) wv[q] = w8[q];
                    #pragma unroll
                    for (int i = 0; i < 2; i++) {
                        #pragma unroll
                        for (int jj = 0; jj < 2; jj++) {
                            const unsigned long long t2 =
                                splat2(tp[i + a][jj + bb2]);
                            #pragma unroll
                            for (int q = 0; q < COUTG / 4; q++) {
                                fma2(acc[i * 2 + jj][2 * q + 0], t2, wv[q].x);
                                fma2(acc[i * 2 + jj][2 * q + 1], t2, wv[q].y);
                            }
                        }
                    }
                }
            }
        }
    }

    // outputs: quads (ty*16+2ggy+i, tx*16+2ggx+jj), pixel (2Y+py, 2X+px)
    #pragma unroll
    for (int j = 0; j < COUTG; j++) {
        if (cog + j >= COUT) break;
        const long long cb = (long long)n * COUT + cog + j;
        #pragma unroll
        for (int i = 0; i < 2; i++) {
            #pragma unroll
            for (int jj = 0; jj < 2; jj++) {
                float tA, tB; unpack2(acc[i * 2 + jj][j >> 1], tA, tB);
                const float v = (j & 1) ? tB : tA;
                const int Y = ty * 16 + 2 * ggy + i;
                const int X = tx * 16 + 2 * ggx + jj;
                out[(cb * HOUT + 2 * Y + py) * WOUT + 2 * X + px] = v;
            }
        }
    }
}

// ------------------------------- batchnorm ---------------------------------
__global__ __launch_bounds__(256)
void bn_stats(const float* __restrict__ x, int C, int HW)
{
    const int c = blockIdx.x >> 5;
    const int s = blockIdx.x & 31;
    const int chunk4 = HW >> 7;

    float sum = 0.f, sq = 0.f;
    for (int n = 0; n < BB; n++) {
        const float4* base = (const float4*)(x + ((long long)(n * C + c)) * HW) +
                             s * chunk4;
        for (int p = threadIdx.x; p < chunk4; p += 256) {
            float4 v = base[p];
            sum += v.x + v.y + v.z + v.w;
            sq = fmaf(v.x, v.x, sq); sq = fmaf(v.y, v.y, sq);
            sq = fmaf(v.z, v.z, sq); sq = fmaf(v.w, v.w, sq);
        }
    }
    __shared__ float s1[256], s2[256];
    s1[threadIdx.x] = sum; s2[threadIdx.x] = sq;
    __syncthreads();
    for (int off = 128; off; off >>= 1) {
        if (threadIdx.x < off) {
            s1[threadIdx.x] += s1[threadIdx.x + off];
            s2[threadIdx.x] += s2[threadIdx.x + off];
        }
        __syncthreads();
    }
    if (threadIdx.x == 0) g_part[blockIdx.x] = make_float2(s1[0], s2[0]);
}

__global__ void bn_finalize(const float* __restrict__ gam,
                            const float* __restrict__ bet, int HW,
                            float* __restrict__ outSc, float* __restrict__ outSh)
{
    const int c = blockIdx.x;
    float2 p = g_part[c * 32 + threadIdx.x];
    double S = p.x, Q = p.y;
    for (int off = 16; off; off >>= 1) {
        S += __shfl_down_sync(0xffffffffu, S, off);
        Q += __shfl_down_sync(0xffffffffu, Q, off);
    }
    if (threadIdx.x == 0) {
        const double P = (double)BB * (double)HW;
        const double mean = S / P;
        const double var  = Q / P - mean * mean;
        const float rstd  = (float)(1.0 / sqrt(var + (double)BN_EPS));
        const float sc = gam[c] * rstd;
        outSc[c] = sc;
        outSh[c] = bet[c] - (float)mean * sc;
    }
}

__global__ __launch_bounds__(256)
void bn_apply_tanh(float* __restrict__ x, int C, int HW, int total4,
                   const float* __restrict__ sc_, const float* __restrict__ sh_)
{
    const int i = blockIdx.x * 256 + threadIdx.x;
    if (i >= total4) return;
    const int hw4 = HW >> 2;
    const int c = (i / hw4) % C;
    const float sc = sc_[c], sh = sh_[c];
    float4 v = ((float4*)x)[i];
    v.x = tanhf(fmaf(v.x, sc, sh)); v.y = tanhf(fmaf(v.y, sc, sh));
    v.z = tanhf(fmaf(v.z, sc, sh)); v.w = tanhf(fmaf(v.w, sc, sh));
    ((float4*)x)[i] = v;
}

// ---------------------------------- VQ -------------------------------------
__global__ void code_norms(const float* __restrict__ cb)
{
    const int k = threadIdx.x;
    float s = 0.f;
    const float* r = cb + k * 64;
    #pragma unroll
    for (int d = 0; d < 64; d++) s = fmaf(r[d], r[d], s);
    g_codeNorm[k] = s;
}

__global__ __launch_bounds__(128)
void vq_argmin(const float* __restrict__ ze, const float* __restrict__ cb,
               const float* __restrict__ sc_, const float* __restrict__ sh_)
{
    __shared__ float sc[64 * 64];
    __shared__ float scn[64];
    __shared__ float red[128];
    __shared__ float ssc[64], ssh[64];

    if (threadIdx.x < 64) {
        ssc[threadIdx.x] = sc_[threadIdx.x];
        ssh[threadIdx.x] = sh_[threadIdx.x];
    }
    __syncthreads();

    const int idx = blockIdx.x * 128 + threadIdx.x;
    const int n  = idx >> 10;
    const int hw = idx & 1023;
    const float* base = ze + (long long)n * 64 * 1024 + hw;

    float z[64];
    #pragma unroll
    for (int d = 0; d < 64; d++)
        z[d] = fmaxf(0.f, fmaf(base[d * 1024], ssc[d], ssh[d]));
    float zz = 0.f;
    #pragma unroll
    for (int d = 0; d < 64; d++) zz = fmaf(z[d], z[d], zz);

    float best = 3.4e38f;
    int   bi   = 0;
    for (int ch = 0; ch < 8; ch++) {
        __syncthreads();
        for (int t = threadIdx.x; t < 1024; t += 128)
            ((float4*)sc)[t] = ((const float4*)(cb + ch * 4096))[t];
        if (threadIdx.x < 64) scn[threadIdx.x] = g_codeNorm[ch * 64 + threadIdx.x];
        __syncthreads();
        #pragma unroll 2
        for (int j = 0; j < 64; j++) {
            const float4* cp = (const float4*)&sc[j * 64];
            float dot = 0.f;
            #pragma unroll
            for (int d4 = 0; d4 < 16; d4++) {
                float4 c4 = cp[d4];
                dot = fmaf(z[4*d4+0], c4.x, dot);
                dot = fmaf(z[4*d4+1], c4.y, dot);
                dot = fmaf(z[4*d4+2], c4.z, dot);
                dot = fmaf(z[4*d4+3], c4.w, dot);
            }
            const float dist = zz - 2.f * dot + scn[j];
            const int k = ch * 64 + j;
            if (dist < best) { best = dist; bi = k; }
        }
    }
    g_idx[idx] = bi;

    const float* cr = cb + bi * 64;
    float e = 0.f;
    #pragma unroll
    for (int d = 0; d < 64; d++) { float df = z[d] - cr[d]; e = fmaf(df, df, e); }

    red[threadIdx.x] = e;
    __syncthreads();
    for (int off = 64; off; off >>= 1) {
        if (threadIdx.x < off) red[threadIdx.x] += red[threadIdx.x + off];
        __syncthreads();
    }
    if (threadIdx.x == 0) g_lossPart[blockIdx.x] = red[0];
}

__global__ void vq_loss_final(float* __restrict__ loss_out)
{
    __shared__ double red[512];
    red[threadIdx.x] = (double)g_lossPart[threadIdx.x];
    __syncthreads();
    for (int off = 256; off; off >>= 1) {
        if (threadIdx.x < off) red[threadIdx.x] += red[threadIdx.x + off];
        __syncthreads();
    }
    if (threadIdx.x == 0)
        loss_out[0] = (float)(2.0 * red[0] / (65536.0 * 64.0));
}

__global__ __launch_bounds__(256)
void vq_scatter(float* __restrict__ q, const float* __restrict__ cb)
{
    const int i = blockIdx.x * 256 + threadIdx.x;
    const int hw = i & 1023;
    const int d  = (i >> 10) & 63;
    const int n  = i >> 16;
    const int code = g_idx[n * 1024 + hw];
    q[i] = cb[code * 64 + d];
}

// -------------------------------- launch -----------------------------------
static inline int nblk(long long total) { return (int)((total + 255) / 256); }

extern "C" void kernel_launch(void* const* d_in, const int* in_sizes, int n_in,
                              void* d_out, int out_size)
{
    (void)in_sizes; (void)n_in;
    const float* x    = (const float*)d_in[0];
    const float* cb   = (const float*)d_in[1];
    const float* eW1  = (const float*)d_in[2];
    const float* eb1  = (const float*)d_in[3];
    const float* eg1  = (const float*)d_in[4];
    const float* ebt1 = (const float*)d_in[5];
    const float* eW2  = (const float*)d_in[6];
    const float* eb2  = (const float*)d_in[7];
    const float* eg2  = (const float*)d_in[8];
    const float* ebt2 = (const float*)d_in[9];
    const float* eW3  = (const float*)d_in[10];
    const float* eb3  = (const float*)d_in[11];
    const float* eg3  = (const float*)d_in[12];
    const float* ebt3 = (const float*)d_in[13];
    const float* dW1  = (const float*)d_in[14];
    const float* db1  = (const float*)d_in[15];
    const float* dg1  = (const float*)d_in[16];
    const float* dbt1 = (const float*)d_in[17];
    const float* dW2  = (const float*)d_in[18];
    const float* db2  = (const float*)d_in[19];
    const float* dg2  = (const float*)d_in[20];
    const float* dbt2 = (const float*)d_in[21];
    const float* dW3  = (const float*)d_in[22];
    const float* db3  = (const float*)d_in[23];
    const float* dg3  = (const float*)d_in[24];
    const float* dbt3 = (const float*)d_in[25];
    float* out = (float*)d_out;

    float *a1, *a2, *a3, *q, *d1, *d2, *bnSc, *bnSh;
    cudaGetSymbolAddress((void**)&a1, g_a1);
    cudaGetSymbolAddress((void**)&a2, g_a2);
    cudaGetSymbolAddress((void**)&a3, g_a3);
    cudaGetSymbolAddress((void**)&q,  g_q);
    cudaGetSymbolAddress((void**)&d1, g_d1);
    cudaGetSymbolAddress((void**)&d2, g_d2);
    cudaGetSymbolAddress((void**)&bnSc, g_bnSc);
    cudaGetSymbolAddress((void**)&bnSh, g_bnSh);
    #define SLOT(i) (bnSc + (i) * 64), (bnSh + (i) * 64)

    // ---------------- encoder ----------------
    // conv1: 3->16 (no fuse). tiles 4x4 x 64 images
    conv_q<3, 16, 16, 1, 256, 256, false><<<dim3(1024, 1), 256>>>(
        x, eW1, eb1, a1, nullptr, nullptr);
    bn_stats<<<16 * 32, 256>>>(a1, 16, 128 * 128);
    bn_finalize<<<16, 32>>>(eg1, ebt1, 128 * 128, SLOT(0));

    // conv2: 16->32, fuse BN0. tiles 2x2 x 64, 2 co-groups
    conv_q<16, 32, 16, 2, 128, 128, true><<<dim3(256, 2), 256>>>(
        a1, eW2, eb2, a2, SLOT(0));
    bn_stats<<<32 * 32, 256>>>(a2, 32, 64 * 64);
    bn_finalize<<<32, 32>>>(eg2, ebt2, 64 * 64, SLOT(1));

    // conv3: 32->64, fuse BN1. tiles 1x1 x 64, 4 co-groups
    conv_q<32, 64, 16, 2, 64, 64, true><<<dim3(64, 4), 256>>>(
        a2, eW3, eb3, a3, SLOT(1));
    bn_stats<<<64 * 32, 256>>>(a3, 64, 32 * 32);
    bn_finalize<<<64, 32>>>(eg3, ebt3, 32 * 32, SLOT(2));

    // ---------------- vector quantization (fuse BN2 into load) -------------
    code_norms<<<1, 512>>>(cb);
    vq_argmin<<<512, 128>>>(a3, cb, SLOT(2));
    vq_loss_final<<<1, 512>>>(out + (out_size - 1));
    vq_scatter<<<nblk((long long)BB * 64 * 32 * 32), 256>>>(q, cb);

    // ---------------- decoder ----------------
    // deconv1: 64->32 (no fuse). quad tiles 2x2 x 64, 2 co-groups
    deconv_q<64, 32, 16, 16, 32, 32, false><<<dim3(256, 2), 256>>>(
        q, dW1, db1, d1, nullptr, nullptr);
    bn_stats<<<32 * 32, 256>>>(d1, 32, 64 * 64);
    bn_finalize<<<32, 32>>>(dg1, dbt1, 64 * 64, SLOT(3));

    // deconv2: 32->16, fuse BN3. quad tiles 4x4 x 64
    deconv_q<32, 16, 16, 16, 64, 64, true><<<dim3(1024, 1), 256>>>(
        d1, dW2, db2, d2, SLOT(3));
    bn_stats<<<16 * 32, 256>>>(d2, 16, 128 * 128);
    bn_finalize<<<16, 32>>>(dg2, dbt2, 128 * 128, SLOT(4));

    // deconv3: 16->3 (COUTG=4, padded), fuse BN4. quad tiles 8x8 x 64
    deconv_q<16, 3, 4, 16, 128, 128, true><<<dim3(4096, 1), 256>>>(
        d2, dW3, db3, out, SLOT(4));
    {
        const long long T = (long long)BB * 3 * 256 * 256;
        bn_stats<<<3 * 32, 256>>>(out, 3, 256 * 256);
        bn_finalize<<<3, 32>>>(dg3, dbt3, 256 * 256, SLOT(5));
        bn_apply_tanh<<<nblk(T / 4), 256>>>(out, 3, 256 * 256, (int)(T / 4), SLOT(5));
    }
    #undef SLOT
}

// round 8
// speedup vs baseline: 1.1052x; 1.0150x over previous
#include <cuda_runtime.h>
#include <math.h>

// ---------------------------------------------------------------------------
// VQ-VAE forward, fp32. 128-thread blocks for occupancy. Conv: 2x2 px/thread,
// per-ky tap rows. Deconv: parity-split 2x2 quad groups. f32x2 FMA. Fused BN.
// ---------------------------------------------------------------------------

#define BB 64
static const float BN_EPS = 1e-5f;

// ------------------------- scratch (device globals) ------------------------
__device__ float g_a1[64 * 16 * 128 * 128];
__device__ float g_a2[64 * 32 * 64 * 64];
__device__ float g_a3[64 * 64 * 32 * 32];
__device__ float g_q [64 * 64 * 32 * 32];
__device__ float g_d1[64 * 32 * 64 * 64];
__device__ float g_d2[64 * 16 * 128 * 128];

__device__ int    g_idx[65536];
__device__ float  g_codeNorm[512];
__device__ float2 g_part[64 * 32];
__device__ float  g_bnSc[6 * 64];
__device__ float  g_bnSh[6 * 64];
__device__ float  g_lossPart[512];

// ---------------------------- f32x2 helpers --------------------------------
__device__ __forceinline__ unsigned long long splat2(float v) {
    unsigned long long r;
    asm("mov.b64 %0, {%1, %1};" : "=l"(r) : "r"(__float_as_uint(v)));
    return r;
}
__device__ __forceinline__ unsigned long long pack2(float a, float b) {
    unsigned long long r;
    asm("mov.b64 %0, {%1, %2};" : "=l"(r)
        : "r"(__float_as_uint(a)), "r"(__float_as_uint(b)));
    return r;
}
__device__ __forceinline__ void unpack2(unsigned long long p, float& a, float& b) {
    unsigned int lo, hi;
    asm("mov.b64 {%0, %1}, %2;" : "=r"(lo), "=r"(hi) : "l"(p));
    a = __uint_as_float(lo); b = __uint_as_float(hi);
}
__device__ __forceinline__ void fma2(unsigned long long& acc,
                                     unsigned long long a, unsigned long long b) {
    asm("fma.rn.f32x2 %0, %1, %2, %0;" : "+l"(acc) : "l"(a), "l"(b));
}

// ------------------------------ conv k4 s2 p1 ------------------------------
// Block (128 thr) = 32x16 output tile; thread = 2x2 pixels x COUTG channels.
// Input patch 34x66 per ci staged in smem (pad 68). Taps per-ky: two 6-wide rows.
template <int CIN, int COUT, int COUTG, int CICHUNK, int HIN, int WIN, bool FUSE>
__global__ __launch_bounds__(128, 5)
void conv_q(const float* __restrict__ in, const float* __restrict__ w,
            const float* __restrict__ bias, float* __restrict__ out,
            const float* __restrict__ bnsc, const float* __restrict__ bnsh)
{
    constexpr int HOUT = HIN / 2, WOUT = WIN / 2;
    constexpr int NBX = WOUT / 32, NBY = HOUT / 16;
    constexpr int TR = 34, TC = 66, TP = 68;

    __shared__ __align__(16) float tile[CICHUNK][TR][TP];
    __shared__ __align__(16) float ws[CICHUNK * 16 * COUTG];

    const int b  = blockIdx.x;
    const int tx = b % NBX;
    const int ty = (b / NBX) % NBY;
    const int n  = b / (NBX * NBY);
    const int cog = blockIdx.y * COUTG;
    const int lx = threadIdx.x & 15, ly = threadIdx.x >> 4;   // 16 x 8

    const int X0 = tx * 64 - 1, Y0 = ty * 32 - 1;
    const float* inn = in + (long long)n * CIN * HIN * WIN;

    unsigned long long acc[4][COUTG / 2];
    #pragma unroll
    for (int j = 0; j < COUTG / 2; j++) {
        const unsigned long long bp =
            pack2(__ldg(&bias[cog + 2 * j]), __ldg(&bias[cog + 2 * j + 1]));
        acc[0][j] = bp; acc[1][j] = bp; acc[2][j] = bp; acc[3][j] = bp;
    }

    for (int ci0 = 0; ci0 < CIN; ci0 += CICHUNK) {
        __syncthreads();
        for (int t = threadIdx.x; t < COUTG * CICHUNK * 16; t += 128) {
            const int j  = t % COUTG;
            const int kk = t / COUTG;
            ws[t] = w[(cog + j) * CIN * 16 + ci0 * 16 + kk];
        }
        for (int t = threadIdx.x; t < CICHUNK * TR * TC; t += 128) {
            const int c  = t / (TR * TC);
            const int r  = (t / TC) % TR;
            const int cc = t % TC;
            const int gyy = Y0 + r, gxx = X0 + cc;
            const bool ok = ((unsigned)gyy < (unsigned)HIN) &&
                            ((unsigned)gxx < (unsigned)WIN);
            float v = ok ?
                __ldg(&inn[((long long)(ci0 + c) * HIN + gyy) * WIN + gxx]) : 0.f;
            if (FUSE && ok)
                v = fmaxf(0.f, fmaf(v, bnsc[ci0 + c], bnsh[ci0 + c]));
            tile[c][r][cc] = v;
        }
        __syncthreads();

        #pragma unroll
        for (int cil = 0; cil < CICHUNK; cil++) {
            #pragma unroll
            for (int ky = 0; ky < 4; ky++) {
                // rows for iy=0 (4ly+ky) and iy=1 (4ly+2+ky), cols 4lx..4lx+5
                float ra[6], rb[6];
                {
                    const float4 a4 = *(const float4*)&tile[cil][4*ly+ky][4*lx];
                    const float2 a2 = *(const float2*)&tile[cil][4*ly+ky][4*lx+4];
                    ra[0]=a4.x; ra[1]=a4.y; ra[2]=a4.z; ra[3]=a4.w; ra[4]=a2.x; ra[5]=a2.y;
                    const float4 b4 = *(const float4*)&tile[cil][4*ly+2+ky][4*lx];
                    const float2 b2 = *(const float2*)&tile[cil][4*ly+2+ky][4*lx+4];
                    rb[0]=b4.x; rb[1]=b4.y; rb[2]=b4.z; rb[3]=b4.w; rb[4]=b2.x; rb[5]=b2.y;
                }
                #pragma unroll
                for (int kx = 0; kx < 4; kx++) {
                    const ulonglong2* w8 =
                        (const ulonglong2*)&ws[(cil * 16 + ky * 4 + kx) * COUTG];
                    ulonglong2 wv[COUTG / 4];
                    #pragma unroll
                    for (int q = 0; q < COUTG / 4; q++) wv[q] = w8[q];
                    #pragma unroll
                    for (int ix = 0; ix < 2; ix++) {
                        const unsigned long long tA = splat2(ra[2 * ix + kx]);
                        const unsigned long long tB = splat2(rb[2 * ix + kx]);
                        #pragma unroll
                        for (int q = 0; q < COUTG / 4; q++) {
                            fma2(acc[ix][2 * q + 0], tA, wv[q].x);
                            fma2(acc[ix][2 * q + 1], tA, wv[q].y);
                            fma2(acc[2 + ix][2 * q + 0], tB, wv[q].x);
                            fma2(acc[2 + ix][2 * q + 1], tB, wv[q].y);
                        }
                    }
                }
            }
        }
    }

    const int oy = ty * 16 + 2 * ly, ox = tx * 32 + 2 * lx;
    #pragma unroll
    for (int j = 0; j < COUTG; j++) {
        float v00, v01, v10, v11, tA, tB;
        unpack2(acc[0][j >> 1], tA, tB); v00 = (j & 1) ? tB : tA;
        unpack2(acc[1][j >> 1], tA, tB); v01 = (j & 1) ? tB : tA;
        unpack2(acc[2][j >> 1], tA, tB); v10 = (j & 1) ? tB : tA;
        unpack2(acc[3][j >> 1], tA, tB); v11 = (j & 1) ? tB : tA;
        const long long cb = (long long)n * COUT + cog + j;
        *(float2*)&out[(cb * HOUT + oy) * WOUT + ox]     = make_float2(v00, v01);
        *(float2*)&out[(cb * HOUT + oy + 1) * WOUT + ox] = make_float2(v10, v11);
    }
}

// --------------------------- deconv k4 s2 p1 -------------------------------
// Block (128 thr) = 16x8 quad tile (32x16 outputs). Thread = parity (py,px)
// of a 2x2 quad group x COUTG channels. Patch 10x18 (pad 20).
template <int CIN, int COUT, int COUTG, int CICHUNK, int HIN, int WIN, bool FUSE>
__global__ __launch_bounds__(128, 5)
void deconv_q(const float* __restrict__ in, const float* __restrict__ w,
              const float* __restrict__ bias, float* __restrict__ out,
              const float* __restrict__ bnsc, const float* __restrict__ bnsh)
{
    constexpr int HOUT = HIN * 2, WOUT = WIN * 2;
    constexpr int NBX = WIN / 16, NBY = HIN / 8;
    constexpr int TR = 10, TC = 18, TP = 20;

    __shared__ float tile[CICHUNK][TR][TP];
    __shared__ __align__(16) float ws[CICHUNK * 16 * COUTG];

    const int b  = blockIdx.x;
    const int tx = b % NBX;
    const int ty = (b / NBX) % NBY;
    const int n  = b / (NBX * NBY);
    const int cog = blockIdx.y * COUTG;

    const int px  = threadIdx.x & 1;
    const int py  = (threadIdx.x >> 1) & 1;
    const int g   = threadIdx.x >> 2;          // 0..31
    const int ggx = g & 7, ggy = g >> 3;       // quad-group coords (8 x 4)

    const float* inn = in + (long long)n * CIN * HIN * WIN;

    unsigned long long acc[4][COUTG / 2];
    #pragma unroll
    for (int j = 0; j < COUTG / 2; j++) {
        const float b0 = (cog + 2*j   < COUT) ? __ldg(&bias[cog + 2*j])   : 0.f;
        const float b1 = (cog + 2*j+1 < COUT) ? __ldg(&bias[cog + 2*j+1]) : 0.f;
        const unsigned long long bp = pack2(b0, b1);
        acc[0][j] = bp; acc[1][j] = bp; acc[2][j] = bp; acc[3][j] = bp;
    }

    const int X0 = tx * 16 - 1, Y0 = ty * 8 - 1;

    for (int ci0 = 0; ci0 < CIN; ci0 += CICHUNK) {
        __syncthreads();
        for (int t = threadIdx.x; t < COUTG * CICHUNK * 16; t += 128) {
            const int j  = t % COUTG;
            const int kk = t / COUTG;
            ws[t] = (cog + j < COUT) ? w[(cog + j) * CIN * 16 + ci0 * 16 + kk] : 0.f;
        }
        for (int t = threadIdx.x; t < CICHUNK * TR * TC; t += 128) {
            const int c  = t / (TR * TC);
            const int r  = (t / TC) % TR;
            const int cc = t % TC;
            const int gyy = Y0 + r, gxx = X0 + cc;
            const bool ok = ((unsigned)gyy < (unsigned)HIN) &&
                            ((unsigned)gxx < (unsigned)WIN);
            float v = ok ?
                __ldg(&inn[((long long)(ci0 + c) * HIN + gyy) * WIN + gxx]) : 0.f;
            if (FUSE && ok)
                v = fmaxf(0.f, fmaf(v, bnsc[ci0 + c], bnsh[ci0 + c]));
            tile[c][r][cc] = v;
        }
        __syncthreads();

        #pragma unroll
        for (int cil = 0; cil < CICHUNK; cil++) {
            float tp[3][3];
            #pragma unroll
            for (int r = 0; r < 3; r++)
                #pragma unroll
                for (int c = 0; c < 3; c++)
                    tp[r][c] = tile[cil][2 * ggy + py + r][2 * ggx + px + c];

            #pragma unroll
            for (int a = 0; a < 2; a++) {
                #pragma unroll
                for (int bb2 = 0; bb2 < 2; bb2++) {
                    const int k = (py + 2 * a) * 4 + (px + 2 * bb2);
                    const ulonglong2* w8 =
                        (const ulonglong2*)&ws[(cil * 16 + k) * COUTG];
                    ulonglong2 wv[COUTG / 4];
                    #pragma unroll
                    for (int q = 0; q < COUTG / 4; q++) wv[q] = w8[q];
                    #pragma unroll
                    for (int i = 0; i < 2; i++) {
                        #pragma unroll
                        for (int jj = 0; jj < 2; jj++) {
                            const unsigned long long t2 =
                                splat2(tp[i + a][jj + bb2]);
                            #pragma unroll
                            for (int q = 0; q < COUTG / 4; q++) {
                                fma2(acc[i * 2 + jj][2 * q + 0], t2, wv[q].x);
                                fma2(acc[i * 2 + jj][2 * q + 1], t2, wv[q].y);
                            }
                        }
                    }
                }
            }
        }
    }

    #pragma unroll
    for (int j = 0; j < COUTG; j++) {
        if (cog + j >= COUT) break;
        const long long cb = (long long)n * COUT + cog + j;
        #pragma unroll
        for (int i = 0; i < 2; i++) {
            #pragma unroll
            for (int jj = 0; jj < 2; jj++) {
                float tA, tB; unpack2(acc[i * 2 + jj][j >> 1], tA, tB);
                const float v = (j & 1) ? tB : tA;
                const int Y = ty * 8 + 2 * ggy + i;
                const int X = tx * 16 + 2 * ggx + jj;
                out[(cb * HOUT + 2 * Y + py) * WOUT + 2 * X + px] = v;
            }
        }
    }
}

// ------------------------------- batchnorm ---------------------------------
__global__ __launch_bounds__(256)
void bn_stats(const float* __restrict__ x, int C, int HW)
{
    const int c = blockIdx.x >> 5;
    const int s = blockIdx.x & 31;
    const int chunk4 = HW >> 7;

    float sum = 0.f, sq = 0.f;
    for (int n = 0; n < BB; n++) {
        const float4* base = (const float4*)(x + ((long long)(n * C + c)) * HW) +
                             s * chunk4;
        for (int p = threadIdx.x; p < chunk4; p += 256) {
            float4 v = base[p];
            sum += v.x + v.y + v.z + v.w;
            sq = fmaf(v.x, v.x, sq); sq = fmaf(v.y, v.y, sq);
            sq = fmaf(v.z, v.z, sq); sq = fmaf(v.w, v.w, sq);
        }
    }
    __shared__ float s1[256], s2[256];
    s1[threadIdx.x] = sum; s2[threadIdx.x] = sq;
    __syncthreads();
    for (int off = 128; off; off >>= 1) {
        if (threadIdx.x < off) {
            s1[threadIdx.x] += s1[threadIdx.x + off];
            s2[threadIdx.x] += s2[threadIdx.x + off];
        }
        __syncthreads();
    }
    if (threadIdx.x == 0) g_part[blockIdx.x] = make_float2(s1[0], s2[0]);
}

__global__ void bn_finalize(const float* __restrict__ gam,
                            const float* __restrict__ bet, int HW,
                            float* __restrict__ outSc, float* __restrict__ outSh)
{
    const int c = blockIdx.x;
    float2 p = g_part[c * 32 + threadIdx.x];
    double S = p.x, Q = p.y;
    for (int off = 16; off; off >>= 1) {
        S += __shfl_down_sync(0xffffffffu, S, off);
        Q += __shfl_down_sync(0xffffffffu, Q, off);
    }
    if (threadIdx.x == 0) {
        const double P = (double)BB * (double)HW;
        const double mean = S / P;
        const double var  = Q / P - mean * mean;
        const float rstd  = (float)(1.0 / sqrt(var + (double)BN_EPS));
        const float sc = gam[c] * rstd;
        outSc[c] = sc;
        outSh[c] = bet[c] - (float)mean * sc;
    }
}

__global__ __launch_bounds__(256)
void bn_apply_tanh(float* __restrict__ x, int C, int HW, int total4,
                   const float* __restrict__ sc_, const float* __restrict__ sh_)
{
    const int i = blockIdx.x * 256 + threadIdx.x;
    if (i >= total4) return;
    const int hw4 = HW >> 2;
    const int c = (i / hw4) % C;
    const float sc = sc_[c], sh = sh_[c];
    float4 v = ((float4*)x)[i];
    v.x = tanhf(fmaf(v.x, sc, sh)); v.y = tanhf(fmaf(v.y, sc, sh));
    v.z = tanhf(fmaf(v.z, sc, sh)); v.w = tanhf(fmaf(v.w, sc, sh));
    ((float4*)x)[i] = v;
}

// ---------------------------------- VQ -------------------------------------
__global__ void code_norms(const float* __restrict__ cb)
{
    const int k = threadIdx.x;
    float s = 0.f;
    const float* r = cb + k * 64;
    #pragma unroll
    for (int d = 0; d < 64; d++) s = fmaf(r[d], r[d], s);
    g_codeNorm[k] = s;
}

__global__ __launch_bounds__(128)
void vq_argmin(const float* __restrict__ ze, const float* __restrict__ cb,
               const float* __restrict__ sc_, const float* __restrict__ sh_)
{
    __shared__ float sc[64 * 64];
    __shared__ float scn[64];
    __shared__ float red[128];
    __shared__ float ssc[64], ssh[64];

    if (threadIdx.x < 64) {
        ssc[threadIdx.x] = sc_[threadIdx.x];
        ssh[threadIdx.x] = sh_[threadIdx.x];
    }
    __syncthreads();

    const int idx = blockIdx.x * 128 + threadIdx.x;
    const int n  = idx >> 10;
    const int hw = idx & 1023;
    const float* base = ze + (long long)n * 64 * 1024 + hw;

    float z[64];
    #pragma unroll
    for (int d = 0; d < 64; d++)
        z[d] = fmaxf(0.f, fmaf(base[d * 1024], ssc[d], ssh[d]));
    float zz = 0.f;
    #pragma unroll
    for (int d = 0; d < 64; d++) zz = fmaf(z[d], z[d], zz);

    float best = 3.4e38f;
    int   bi   = 0;
    for (int ch = 0; ch < 8; ch++) {
        __syncthreads();
        for (int t = threadIdx.x; t < 1024; t += 128)
            ((float4*)sc)[t] = ((const float4*)(cb + ch * 4096))[t];
        if (threadIdx.x < 64) scn[threadIdx.x] = g_codeNorm[ch * 64 + threadIdx.x];
        __syncthreads();
        #pragma unroll 2
        for (int j = 0; j < 64; j++) {
            const float4* cp = (const float4*)&sc[j * 64];
            float dot = 0.f;
            #pragma unroll
            for (int d4 = 0; d4 < 16; d4++) {
                float4 c4 = cp[d4];
                dot = fmaf(z[4*d4+0], c4.x, dot);
                dot = fmaf(z[4*d4+1], c4.y, dot);
                dot = fmaf(z[4*d4+2], c4.z, dot);
                dot = fmaf(z[4*d4+3], c4.w, dot);
            }
            const float dist = zz - 2.f * dot + scn[j];
            const int k = ch * 64 + j;
            if (dist < best) { best = dist; bi = k; }
        }
    }
    g_idx[idx] = bi;

    const float* cr = cb + bi * 64;
    float e = 0.f;
    #pragma unroll
    for (int d = 0; d < 64; d++) { float df = z[d] - cr[d]; e = fmaf(df, df, e); }

    red[threadIdx.x] = e;
    __syncthreads();
    for (int off = 64; off; off >>= 1) {
        if (threadIdx.x < off) red[threadIdx.x] += red[threadIdx.x + off];
        __syncthreads();
    }
    if (threadIdx.x == 0) g_lossPart[blockIdx.x] = red[0];
}

__global__ void vq_loss_final(float* __restrict__ loss_out)
{
    __shared__ double red[512];
    red[threadIdx.x] = (double)g_lossPart[threadIdx.x];
    __syncthreads();
    for (int off = 256; off; off >>= 1) {
        if (threadIdx.x < off) red[threadIdx.x] += red[threadIdx.x + off];
        __syncthreads();
    }
    if (threadIdx.x == 0)
        loss_out[0] = (float)(2.0 * red[0] / (65536.0 * 64.0));
}

__global__ __launch_bounds__(256)
void vq_scatter(float* __restrict__ q, const float* __restrict__ cb)
{
    const int i = blockIdx.x * 256 + threadIdx.x;
    const int hw = i & 1023;
    const int d  = (i >> 10) & 63;
    const int n  = i >> 16;
    const int code = g_idx[n * 1024 + hw];
    q[i] = cb[code * 64 + d];
}

// -------------------------------- launch -----------------------------------
static inline int nblk(long long total) { return (int)((total + 255) / 256); }

extern "C" void kernel_launch(void* const* d_in, const int* in_sizes, int n_in,
                              void* d_out, int out_size)
{
    (void)in_sizes; (void)n_in;
    const float* x    = (const float*)d_in[0];
    const float* cb   = (const float*)d_in[1];
    const float* eW1  = (const float*)d_in[2];
    const float* eb1  = (const float*)d_in[3];
    const float* eg1  = (const float*)d_in[4];
    const float* ebt1 = (const float*)d_in[5];
    const float* eW2  = (const float*)d_in[6];
    const float* eb2  = (const float*)d_in[7];
    const float* eg2  = (const float*)d_in[8];
    const float* ebt2 = (const float*)d_in[9];
    const float* eW3  = (const float*)d_in[10];
    const float* eb3  = (const float*)d_in[11];
    const float* eg3  = (const float*)d_in[12];
    const float* ebt3 = (const float*)d_in[13];
    const float* dW1  = (const float*)d_in[14];
    const float* db1  = (const float*)d_in[15];
    const float* dg1  = (const float*)d_in[16];
    const float* dbt1 = (const float*)d_in[17];
    const float* dW2  = (const float*)d_in[18];
    const float* db2  = (const float*)d_in[19];
    const float* dg2  = (const float*)d_in[20];
    const float* dbt2 = (const float*)d_in[21];
    const float* dW3  = (const float*)d_in[22];
    const float* db3  = (const float*)d_in[23];
    const float* dg3  = (const float*)d_in[24];
    const float* dbt3 = (const float*)d_in[25];
    float* out = (float*)d_out;

    float *a1, *a2, *a3, *q, *d1, *d2, *bnSc, *bnSh;
    cudaGetSymbolAddress((void**)&a1, g_a1);
    cudaGetSymbolAddress((void**)&a2, g_a2);
    cudaGetSymbolAddress((void**)&a3, g_a3);
    cudaGetSymbolAddress((void**)&q,  g_q);
    cudaGetSymbolAddress((void**)&d1, g_d1);
    cudaGetSymbolAddress((void**)&d2, g_d2);
    cudaGetSymbolAddress((void**)&bnSc, g_bnSc);
    cudaGetSymbolAddress((void**)&bnSh, g_bnSh);
    #define SLOT(i) (bnSc + (i) * 64), (bnSh + (i) * 64)

    // ---------------- encoder ----------------
    // conv1: 3->16 (no fuse). tiles 4x8 x 64 = 2048 blocks
    conv_q<3, 16, 16, 1, 256, 256, false><<<dim3(2048, 1), 128>>>(
        x, eW1, eb1, a1, nullptr, nullptr);
    bn_stats<<<16 * 32, 256>>>(a1, 16, 128 * 128);
    bn_finalize<<<16, 32>>>(eg1, ebt1, 128 * 128, SLOT(0));

    // conv2: 16->32, fuse BN0. tiles 2x4 x 64 = 512, 2 co-groups
    conv_q<16, 32, 16, 2, 128, 128, true><<<dim3(512, 2), 128>>>(
        a1, eW2, eb2, a2, SLOT(0));
    bn_stats<<<32 * 32, 256>>>(a2, 32, 64 * 64);
    bn_finalize<<<32, 32>>>(eg2, ebt2, 64 * 64, SLOT(1));

    // conv3: 32->64, fuse BN1. tiles 1x2 x 64 = 128, 4 co-groups
    conv_q<32, 64, 16, 2, 64, 64, true><<<dim3(128, 4), 128>>>(
        a2, eW3, eb3, a3, SLOT(1));
    bn_stats<<<64 * 32, 256>>>(a3, 64, 32 * 32);
    bn_finalize<<<64, 32>>>(eg3, ebt3, 32 * 32, SLOT(2));

    // ---------------- vector quantization (fuse BN2 into load) -------------
    code_norms<<<1, 512>>>(cb);
    vq_argmin<<<512, 128>>>(a3, cb, SLOT(2));
    vq_loss_final<<<1, 512>>>(out + (out_size - 1));
    vq_scatter<<<nblk((long long)BB * 64 * 32 * 32), 256>>>(q, cb);

    // ---------------- decoder ----------------
    // deconv1: 64->32 (no fuse). quad tiles 2x4 x 64 = 512, 2 co-groups
    deconv_q<64, 32, 16, 8, 32, 32, false><<<dim3(512, 2), 128>>>(
        q, dW1, db1, d1, nullptr, nullptr);
    bn_stats<<<32 * 32, 256>>>(d1, 32, 64 * 64);
    bn_finalize<<<32, 32>>>(dg1, dbt1, 64 * 64, SLOT(3));

    // deconv2: 32->16, fuse BN3. quad tiles 4x8 x 64 = 2048
    deconv_q<32, 16, 16, 8, 64, 64, true><<<dim3(2048, 1), 128>>>(
        d1, dW2, db2, d2, SLOT(3));
    bn_stats<<<16 * 32, 256>>>(d2, 16, 128 * 128);
    bn_finalize<<<16, 32>>>(dg2, dbt2, 128 * 128, SLOT(4));

    // deconv3: 16->3 (COUTG=4 padded), fuse BN4. quad tiles 8x16 x 64 = 8192
    deconv_q<16, 3, 4, 16, 128, 128, true><<<dim3(8192, 1), 128>>>(
        d2, dW3, db3, out, SLOT(4));
    {
        const long long T = (long long)BB * 3 * 256 * 256;
        bn_stats<<<3 * 32, 256>>>(out, 3, 256 * 256);
        bn_finalize<<<3, 32>>>(dg3, dbt3, 256 * 256, SLOT(5));
        bn_apply_tanh<<<nblk(T / 4), 256>>>(out, 3, 256 * 256, (int)(T / 4), SLOT(5));
    }
    #undef SLOT
}

// round 10
// speedup vs baseline: 1.2256x; 1.1089x over previous
#include <cuda_runtime.h>
#include <math.h>

// ---------------------------------------------------------------------------
// VQ-VAE forward. Encoder: scalar fp32 (f32x2 FMA). Decoder: TF32 mma.sync
// implicit GEMM (4-parity decomposition of deconv k4s2). BN fused into
// consumers; exact fp32 VQ argmin.
// ---------------------------------------------------------------------------

#define BB 64
static const float BN_EPS = 1e-5f;

// ------------------------- scratch (device globals) ------------------------
__device__ float g_a1[64 * 16 * 128 * 128];
__device__ float g_a2[64 * 32 * 64 * 64];
__device__ float g_a3[64 * 64 * 32 * 32];
__device__ float g_q [64 * 64 * 32 * 32];
__device__ float g_d1[64 * 32 * 64 * 64];
__device__ float g_d2[64 * 16 * 128 * 128];

__device__ int    g_idx[65536];
__device__ float  g_codeNorm[512];
__device__ float2 g_part[64 * 32];
__device__ float  g_bnSc[6 * 64];
__device__ float  g_bnSh[6 * 64];
__device__ float  g_lossPart[512];

// ---------------------------- f32x2 helpers --------------------------------
__device__ __forceinline__ unsigned long long splat2(float v) {
    unsigned long long r;
    asm("mov.b64 %0, {%1, %1};" : "=l"(r) : "r"(__float_as_uint(v)));
    return r;
}
__device__ __forceinline__ unsigned long long pack2(float a, float b) {
    unsigned long long r;
    asm("mov.b64 %0, {%1, %2};" : "=l"(r)
        : "r"(__float_as_uint(a)), "r"(__float_as_uint(b)));
    return r;
}
__device__ __forceinline__ void unpack2(unsigned long long p, float& a, float& b) {
    unsigned int lo, hi;
    asm("mov.b64 {%0, %1}, %2;" : "=r"(lo), "=r"(hi) : "l"(p));
    a = __uint_as_float(lo); b = __uint_as_float(hi);
}
__device__ __forceinline__ void fma2(unsigned long long& acc,
                                     unsigned long long a, unsigned long long b) {
    asm("fma.rn.f32x2 %0, %1, %2, %0;" : "+l"(acc) : "l"(a), "l"(b));
}

// ---------------------------- tf32 mma helpers -----------------------------
__device__ __forceinline__ unsigned int f2tf(float x) {
    unsigned int r;
    asm("cvt.rna.tf32.f32 %0, %1;" : "=r"(r) : "f"(x));
    return r;
}
__device__ __forceinline__ void mma_tf32(float* c, const unsigned int* a,
                                         const unsigned int* b) {
    asm volatile(
        "mma.sync.aligned.m16n8k8.row.col.f32.tf32.tf32.f32 "
        "{%0,%1,%2,%3}, {%4,%5,%6,%7}, {%8,%9}, {%0,%1,%2,%3};"
        : "+f"(c[0]), "+f"(c[1]), "+f"(c[2]), "+f"(c[3])
        : "r"(a[0]), "r"(a[1]), "r"(a[2]), "r"(a[3]), "r"(b[0]), "r"(b[1]));
}

// ------------------------------ conv k4 s2 p1 (scalar, encoder) ------------
template <int CIN, int COUT, int COUTG, int CICHUNK, int HIN, int WIN, bool FUSE>
__global__ __launch_bounds__(128, 5)
void conv_q(const float* __restrict__ in, const float* __restrict__ w,
            const float* __restrict__ bias, float* __restrict__ out,
            const float* __restrict__ bnsc, const float* __restrict__ bnsh)
{
    constexpr int HOUT = HIN / 2, WOUT = WIN / 2;
    constexpr int NBX = WOUT / 32, NBY = HOUT / 16;
    constexpr int TR = 34, TC = 66, TP = 68;

    __shared__ __align__(16) float tile[CICHUNK][TR][TP];
    __shared__ __align__(16) float ws[CICHUNK * 16 * COUTG];

    const int b  = blockIdx.x;
    const int tx = b % NBX;
    const int ty = (b / NBX) % NBY;
    const int n  = b / (NBX * NBY);
    const int cog = blockIdx.y * COUTG;
    const int lx = threadIdx.x & 15, ly = threadIdx.x >> 4;

    const int X0 = tx * 64 - 1, Y0 = ty * 32 - 1;
    const float* inn = in + (long long)n * CIN * HIN * WIN;

    unsigned long long acc[4][COUTG / 2];
    #pragma unroll
    for (int j = 0; j < COUTG / 2; j++) {
        const unsigned long long bp =
            pack2(__ldg(&bias[cog + 2 * j]), __ldg(&bias[cog + 2 * j + 1]));
        acc[0][j] = bp; acc[1][j] = bp; acc[2][j] = bp; acc[3][j] = bp;
    }

    for (int ci0 = 0; ci0 < CIN; ci0 += CICHUNK) {
        __syncthreads();
        for (int t = threadIdx.x; t < COUTG * CICHUNK * 16; t += 128) {
            const int j  = t % COUTG;
            const int kk = t / COUTG;
            ws[t] = w[(cog + j) * CIN * 16 + ci0 * 16 + kk];
        }
        for (int t = threadIdx.x; t < CICHUNK * TR * TC; t += 128) {
            const int c  = t / (TR * TC);
            const int r  = (t / TC) % TR;
            const int cc = t % TC;
            const int gyy = Y0 + r, gxx = X0 + cc;
            const bool ok = ((unsigned)gyy < (unsigned)HIN) &&
                            ((unsigned)gxx < (unsigned)WIN);
            float v = ok ?
                __ldg(&inn[((long long)(ci0 + c) * HIN + gyy) * WIN + gxx]) : 0.f;
            if (FUSE && ok)
                v = fmaxf(0.f, fmaf(v, bnsc[ci0 + c], bnsh[ci0 + c]));
            tile[c][r][cc] = v;
        }
        __syncthreads();

        #pragma unroll
        for (int cil = 0; cil < CICHUNK; cil++) {
            #pragma unroll
            for (int ky = 0; ky < 4; ky++) {
                float ra[6], rb[6];
                {
                    const float4 a4 = *(const float4*)&tile[cil][4*ly+ky][4*lx];
                    const float2 a2 = *(const float2*)&tile[cil][4*ly+ky][4*lx+4];
                    ra[0]=a4.x; ra[1]=a4.y; ra[2]=a4.z; ra[3]=a4.w; ra[4]=a2.x; ra[5]=a2.y;
                    const float4 b4 = *(const float4*)&tile[cil][4*ly+2+ky][4*lx];
                    const float2 b2 = *(const float2*)&tile[cil][4*ly+2+ky][4*lx+4];
                    rb[0]=b4.x; rb[1]=b4.y; rb[2]=b4.z; rb[3]=b4.w; rb[4]=b2.x; rb[5]=b2.y;
                }
                #pragma unroll
                for (int kx = 0; kx < 4; kx++) {
                    const ulonglong2* w8 =
                        (const ulonglong2*)&ws[(cil * 16 + ky * 4 + kx) * COUTG];
                    ulonglong2 wv[COUTG / 4];
                    #pragma unroll
                    for (int q = 0; q < COUTG / 4; q++) wv[q] = w8[q];
                    #pragma unroll
                    for (int ix = 0; ix < 2; ix++) {
                        const unsigned long long tA = splat2(ra[2 * ix + kx]);
                        const unsigned long long tB = splat2(rb[2 * ix + kx]);
                        #pragma unroll
                        for (int q = 0; q < COUTG / 4; q++) {
                            fma2(acc[ix][2 * q + 0], tA, wv[q].x);
                            fma2(acc[ix][2 * q + 1], tA, wv[q].y);
                            fma2(acc[2 + ix][2 * q + 0], tB, wv[q].x);
                            fma2(acc[2 + ix][2 * q + 1], tB, wv[q].y);
                        }
                    }
                }
            }
        }
    }

    const int oy = ty * 16 + 2 * ly, ox = tx * 32 + 2 * lx;
    #pragma unroll
    for (int j = 0; j < COUTG; j++) {
        float v00, v01, v10, v11, tA, tB;
        unpack2(acc[0][j >> 1], tA, tB); v00 = (j & 1) ? tB : tA;
        unpack2(acc[1][j >> 1], tA, tB); v01 = (j & 1) ? tB : tA;
        unpack2(acc[2][j >> 1], tA, tB); v10 = (j & 1) ? tB : tA;
        unpack2(acc[3][j >> 1], tA, tB); v11 = (j & 1) ? tB : tA;
        const long long cb = (long long)n * COUT + cog + j;
        *(float2*)&out[(cb * HOUT + oy) * WOUT + ox]     = make_float2(v00, v01);
        *(float2*)&out[(cb * HOUT + oy + 1) * WOUT + ox] = make_float2(v10, v11);
    }
}

// --------------------- deconv k4 s2 p1 via TF32 mma ------------------------
// Per parity (py,px): out(2Y+py,2X+px) = Σ_{a,b,ci} in[Y-1+py+a, X-1+px+b, ci]
//                                        * W[co, ci, py+2a, px+2b]
// Block (256 thr / 8 warps) = 16x8 quad tile. Warp: parity (py,px), half h.
// KC = ci chunk (8 or 16); mma-K steps per tap = KC/8.
template <int CIN, int COUT, int NT, int KC, int HIN, int WIN, bool FUSE>
__global__ __launch_bounds__(256)
void deconv_mma(const float* __restrict__ in, const float* __restrict__ w,
                const float* __restrict__ bias, float* __restrict__ out,
                const float* __restrict__ bnsc, const float* __restrict__ bnsh)
{
    constexpr int COPAD = COUT + 8;
    constexpr int HOUT = 2 * HIN, WOUT = 2 * WIN;
    constexpr int NBX = WIN / 16, NBY = HIN / 8;

    __shared__ float tile[KC][10][20];
    __shared__ float wB[16 * KC * COPAD];   // [tap][ciLocal][coPad]

    const int b  = blockIdx.x;
    const int tx = b % NBX;
    const int ty = (b / NBX) % NBY;
    const int n  = b / (NBX * NBY);
    const int X0 = tx * 16, Y0 = ty * 8;

    const int lane = threadIdx.x & 31;
    const int wid  = threadIdx.x >> 5;
    const int px = wid & 1, py = (wid >> 1) & 1, h = wid >> 2;

    const float* inn = in + (long long)n * CIN * HIN * WIN;

    float acc[4][NT][4];
    #pragma unroll
    for (int nt = 0; nt < NT; nt++) {
        const int co0 = nt * 8 + 2 * (lane & 3);
        const float b0 = (co0     < COUT) ? __ldg(&bias[co0])     : 0.f;
        const float b1 = (co0 + 1 < COUT) ? __ldg(&bias[co0 + 1]) : 0.f;
        #pragma unroll
        for (int mt = 0; mt < 4; mt++) {
            acc[mt][nt][0] = b0; acc[mt][nt][1] = b1;
            acc[mt][nt][2] = b0; acc[mt][nt][3] = b1;
        }
    }

    for (int ci0 = 0; ci0 < CIN; ci0 += KC) {
        __syncthreads();
        // stage weights: wB[tap][ci][coPad]
        for (int t = threadIdx.x; t < 16 * KC * COPAD; t += 256) {
            const int co  = t % COPAD;
            const int rem = t / COPAD;
            const int ci  = rem % KC;
            const int tap = rem / KC;
            wB[t] = (co < COUT) ? __ldg(&w[(co * CIN + ci0 + ci) * 16 + tap]) : 0.f;
        }
        // stage input patch 10x18 (pad 20) per ci
        for (int t = threadIdx.x; t < KC * 10 * 18; t += 256) {
            const int cc  = t % 18;
            const int rem = t / 18;
            const int r   = rem % 10;
            const int c   = rem / 10;
            const int gy = Y0 - 1 + r, gx = X0 - 1 + cc;
            const bool ok = ((unsigned)gy < (unsigned)HIN) &&
                            ((unsigned)gx < (unsigned)WIN);
            float v = ok ?
                __ldg(&inn[((long long)(ci0 + c) * HIN + gy) * WIN + gx]) : 0.f;
            if (FUSE && ok)
                v = fmaxf(0.f, fmaf(v, bnsc[ci0 + c], bnsh[ci0 + c]));
            tile[c][r][cc] = v;
        }
        __syncthreads();

        #pragma unroll
        for (int a = 0; a < 2; a++) {
            #pragma unroll
            for (int bs = 0; bs < 2; bs++) {
                const int tap = (py + 2 * a) * 4 + (px + 2 * bs);
                const float* wT = &wB[tap * KC * COPAD];
                const int xA = (lane >> 2) + px + bs;
                #pragma unroll
                for (int kk = 0; kk < KC / 8; kk++) {
                    const int kA = kk * 8 + (lane & 3);
                    unsigned int A[4][4];
                    #pragma unroll
                    for (int mt = 0; mt < 4; mt++) {
                        const int yA = h * 4 + mt + py + a;
                        A[mt][0] = f2tf(tile[kA][yA][xA]);
                        A[mt][1] = f2tf(tile[kA][yA][xA + 8]);
                        A[mt][2] = f2tf(tile[kA + 4][yA][xA]);
                        A[mt][3] = f2tf(tile[kA + 4][yA][xA + 8]);
                    }
                    #pragma unroll
                    for (int nt = 0; nt < NT; nt++) {
                        unsigned int Bf[2];
                        const int coL = nt * 8 + (lane >> 2);
                        Bf[0] = f2tf(wT[kA * COPAD + coL]);
                        Bf[1] = f2tf(wT[(kA + 4) * COPAD + coL]);
                        #pragma unroll
                        for (int mt = 0; mt < 4; mt++)
                            mma_tf32(acc[mt][nt], A[mt], Bf);
                    }
                }
            }
        }
    }

    // writeback: mtile mt -> quad row Yq = Y0 + h*4 + mt; cols qx=lane>>2, +8
    #pragma unroll
    for (int mt = 0; mt < 4; mt++) {
        const int orow = 2 * (Y0 + h * 4 + mt) + py;
        const int qx0 = lane >> 2;
        const int ox0 = 2 * (X0 + qx0) + px;
        const int ox1 = 2 * (X0 + qx0 + 8) + px;
        #pragma unroll
        for (int nt = 0; nt < NT; nt++) {
            const int co0 = nt * 8 + 2 * (lane & 3);
            if (co0 < COUT) {
                float* rowp = out + (((long long)n * COUT + co0) * HOUT + orow) * WOUT;
                rowp[ox0] = acc[mt][nt][0];
                rowp[ox1] = acc[mt][nt][2];
            }
            if (co0 + 1 < COUT) {
                float* rowp = out + (((long long)n * COUT + co0 + 1) * HOUT + orow) * WOUT;
                rowp[ox0] = acc[mt][nt][1];
                rowp[ox1] = acc[mt][nt][3];
            }
        }
    }
}

// ------------------------------- batchnorm ---------------------------------
__global__ __launch_bounds__(256)
void bn_stats(const float* __restrict__ x, int C, int HW)
{
    const int c = blockIdx.x >> 5;
    const int s = blockIdx.x & 31;
    const int chunk4 = HW >> 7;

    float sum = 0.f, sq = 0.f;
    for (int n = 0; n < BB; n++) {
        const float4* base = (const float4*)(x + ((long long)(n * C + c)) * HW) +
                             s * chunk4;
        for (int p = threadIdx.x; p < chunk4; p += 256) {
            float4 v = base[p];
            sum += v.x + v.y + v.z + v.w;
            sq = fmaf(v.x, v.x, sq); sq = fmaf(v.y, v.y, sq);
            sq = fmaf(v.z, v.z, sq); sq = fmaf(v.w, v.w, sq);
        }
    }
    __shared__ float s1[256], s2[256];
    s1[threadIdx.x] = sum; s2[threadIdx.x] = sq;
    __syncthreads();
    for (int off = 128; off; off >>= 1) {
        if (threadIdx.x < off) {
            s1[threadIdx.x] += s1[threadIdx.x + off];
            s2[threadIdx.x] += s2[threadIdx.x + off];
        }
        __syncthreads();
    }
    if (threadIdx.x == 0) g_part[blockIdx.x] = make_float2(s1[0], s2[0]);
}

__global__ void bn_finalize(const float* __restrict__ gam,
                            const float* __restrict__ bet, int HW,
                            float* __restrict__ outSc, float* __restrict__ outSh)
{
    const int c = blockIdx.x;
    float2 p = g_part[c * 32 + threadIdx.x];
    double S = p.x, Q = p.y;
    for (int off = 16; off; off >>= 1) {
        S += __shfl_down_sync(0xffffffffu, S, off);
        Q += __shfl_down_sync(0xffffffffu, Q, off);
    }
    if (threadIdx.x == 0) {
        const double P = (double)BB * (double)HW;
        const double mean = S / P;
        const double var  = Q / P - mean * mean;
        const float rstd  = (float)(1.0 / sqrt(var + (double)BN_EPS));
        const float sc = gam[c] * rstd;
        outSc[c] = sc;
        outSh[c] = bet[c] - (float)mean * sc;
    }
}

__global__ __launch_bounds__(256)
void bn_apply_tanh(float* __restrict__ x, int C, int HW, int total4,
                   const float* __restrict__ sc_, const float* __restrict__ sh_)
{
    const int i = blockIdx.x * 256 + threadIdx.x;
    if (i >= total4) return;
    const int hw4 = HW >> 2;
    const int c = (i / hw4) % C;
    const float sc = sc_[c], sh = sh_[c];
    float4 v = ((float4*)x)[i];
    v.x = tanhf(fmaf(v.x, sc, sh)); v.y = tanhf(fmaf(v.y, sc, sh));
    v.z = tanhf(fmaf(v.z, sc, sh)); v.w = tanhf(fmaf(v.w, sc, sh));
    ((float4*)x)[i] = v;
}

// ---------------------------------- VQ -------------------------------------
__global__ void code_norms(const float* __restrict__ cb)
{
    const int k = threadIdx.x;
    float s = 0.f;
    const float* r = cb + k * 64;
    #pragma unroll
    for (int d = 0; d < 64; d++) s = fmaf(r[d], r[d], s);
    g_codeNorm[k] = s;
}

__global__ __launch_bounds__(128)
void vq_argmin(const float* __restrict__ ze, const float* __restrict__ cb,
               const float* __restrict__ sc_, const float* __restrict__ sh_)
{
    __shared__ float sc[64 * 64];
    __shared__ float scn[64];
    __shared__ float red[128];
    __shared__ float ssc[64], ssh[64];

    if (threadIdx.x < 64) {
        ssc[threadIdx.x] = sc_[threadIdx.x];
        ssh[threadIdx.x] = sh_[threadIdx.x];
    }
    __syncthreads();

    const int idx = blockIdx.x * 128 + threadIdx.x;
    const int n  = idx >> 10;
    const int hw = idx & 1023;
    const float* base = ze + (long long)n * 64 * 1024 + hw;

    float z[64];
    #pragma unroll
    for (int d = 0; d < 64; d++)
        z[d] = fmaxf(0.f, fmaf(base[d * 1024], ssc[d], ssh[d]));
    float zz = 0.f;
    #pragma unroll
    for (int d = 0; d < 64; d++) zz = fmaf(z[d], z[d], zz);

    float best = 3.4e38f;
    int   bi   = 0;
    for (int ch = 0; ch < 8; ch++) {
        __syncthreads();
        for (int t = threadIdx.x; t < 1024; t += 128)
            ((float4*)sc)[t] = ((const float4*)(cb + ch * 4096))[t];
        if (threadIdx.x < 64) scn[threadIdx.x] = g_codeNorm[ch * 64 + threadIdx.x];
        __syncthreads();
        #pragma unroll 2
        for (int j = 0; j < 64; j++) {
            const float4* cp = (const float4*)&sc[j * 64];
            float dot = 0.f;
            #pragma unroll
            for (int d4 = 0; d4 < 16; d4++) {
                float4 c4 = cp[d4];
                dot = fmaf(z[4*d4+0], c4.x, dot);
                dot = fmaf(z[4*d4+1], c4.y, dot);
                dot = fmaf(z[4*d4+2], c4.z, dot);
                dot = fmaf(z[4*d4+3], c4.w, dot);
            }
            const float dist = zz - 2.f * dot + scn[j];
            const int k = ch * 64 + j;
            if (dist < best) { best = dist; bi = k; }
        }
    }
    g_idx[idx] = bi;

    const float* cr = cb + bi * 64;
    float e = 0.f;
    #pragma unroll
    for (int d = 0; d < 64; d++) { float df = z[d] - cr[d]; e = fmaf(df, df, e); }

    red[threadIdx.x] = e;
    __syncthreads();
    for (int off = 64; off; off >>= 1) {
        if (threadIdx.x < off) red[threadIdx.x] += red[threadIdx.x + off];
        __syncthreads();
    }
    if (threadIdx.x == 0) g_lossPart[blockIdx.x] = red[0];
}

__global__ void vq_loss_final(float* __restrict__ loss_out)
{
    __shared__ double red[512];
    red[threadIdx.x] = (double)g_lossPart[threadIdx.x];
    __syncthreads();
    for (int off = 256; off; off >>= 1) {
        if (threadIdx.x < off) red[threadIdx.x] += red[threadIdx.x + off];
        __syncthreads();
    }
    if (threadIdx.x == 0)
        loss_out[0] = (float)(2.0 * red[0] / (65536.0 * 64.0));
}

__global__ __launch_bounds__(256)
void vq_scatter(float* __restrict__ q, const float* __restrict__ cb)
{
    const int i = blockIdx.x * 256 + threadIdx.x;
    const int hw = i & 1023;
    const int d  = (i >> 10) & 63;
    const int n  = i >> 16;
    const int code = g_idx[n * 1024 + hw];
    q[i] = cb[code * 64 + d];
}

// -------------------------------- launch -----------------------------------
static inline int nblk(long long total) { return (int)((total + 255) / 256); }

extern "C" void kernel_launch(void* const* d_in, const int* in_sizes, int n_in,
                              void* d_out, int out_size)
{
    (void)in_sizes; (void)n_in;
    const float* x    = (const float*)d_in[0];
    const float* cb   = (const float*)d_in[1];
    const float* eW1  = (const float*)d_in[2];
    const float* eb1  = (const float*)d_in[3];
    const float* eg1  = (const float*)d_in[4];
    const float* ebt1 = (const float*)d_in[5];
    const float* eW2  = (const float*)d_in[6];
    const float* eb2  = (const float*)d_in[7];
    const float* eg2  = (const float*)d_in[8];
    const float* ebt2 = (const float*)d_in[9];
    const float* eW3  = (const float*)d_in[10];
    const float* eb3  = (const float*)d_in[11];
    const float* eg3  = (const float*)d_in[12];
    const float* ebt3 = (const float*)d_in[13];
    const float* dW1  = (const float*)d_in[14];
    const float* db1  = (const float*)d_in[15];
    const float* dg1  = (const float*)d_in[16];
    const float* dbt1 = (const float*)d_in[17];
    const float* dW2  = (const float*)d_in[18];
    const float* db2  = (const float*)d_in[19];
    const float* dg2  = (const float*)d_in[20];
    const float* dbt2 = (const float*)d_in[21];
    const float* dW3  = (const float*)d_in[22];
    const float* db3  = (const float*)d_in[23];
    const float* dg3  = (const float*)d_in[24];
    const float* dbt3 = (const float*)d_in[25];
    float* out = (float*)d_out;

    float *a1, *a2, *a3, *q, *d1, *d2, *bnSc, *bnSh;
    cudaGetSymbolAddress((void**)&a1, g_a1);
    cudaGetSymbolAddress((void**)&a2, g_a2);
    cudaGetSymbolAddress((void**)&a3, g_a3);
    cudaGetSymbolAddress((void**)&q,  g_q);
    cudaGetSymbolAddress((void**)&d1, g_d1);
    cudaGetSymbolAddress((void**)&d2, g_d2);
    cudaGetSymbolAddress((void**)&bnSc, g_bnSc);
    cudaGetSymbolAddress((void**)&bnSh, g_bnSh);
    #define SLOT(i) (bnSc + (i) * 64), (bnSh + (i) * 64)

    // ---------------- encoder (scalar fp32) ----------------
    conv_q<3, 16, 16, 1, 256, 256, false><<<dim3(2048, 1), 128>>>(
        x, eW1, eb1, a1, nullptr, nullptr);
    bn_stats<<<16 * 32, 256>>>(a1, 16, 128 * 128);
    bn_finalize<<<16, 32>>>(eg1, ebt1, 128 * 128, SLOT(0));

    conv_q<16, 32, 16, 2, 128, 128, true><<<dim3(512, 2), 128>>>(
        a1, eW2, eb2, a2, SLOT(0));
    bn_stats<<<32 * 32, 256>>>(a2, 32, 64 * 64);
    bn_finalize<<<32, 32>>>(eg2, ebt2, 64 * 64, SLOT(1));

    conv_q<32, 64, 16, 2, 64, 64, true><<<dim3(128, 4), 128>>>(
        a2, eW3, eb3, a3, SLOT(1));
    bn_stats<<<64 * 32, 256>>>(a3, 64, 32 * 32);
    bn_finalize<<<64, 32>>>(eg3, ebt3, 32 * 32, SLOT(2));

    // ---------------- vector quantization (exact fp32) ----------------
    code_norms<<<1, 512>>>(cb);
    vq_argmin<<<512, 128>>>(a3, cb, SLOT(2));
    vq_loss_final<<<1, 512>>>(out + (out_size - 1));
    vq_scatter<<<nblk((long long)BB * 64 * 32 * 32), 256>>>(q, cb);

    // ---------------- decoder (TF32 mma) ----------------
    // deconv1: 64->32, 32x32 in. KC=8 (smem fits). 512 blocks, NT=4
    deconv_mma<64, 32, 4, 8, 32, 32, false><<<512, 256>>>(
        q, dW1, db1, d1, nullptr, nullptr);
    bn_stats<<<32 * 32, 256>>>(d1, 32, 64 * 64);
    bn_finalize<<<32, 32>>>(dg1, dbt1, 64 * 64, SLOT(3));

    // deconv2: 32->16, 64x64 in. KC=16. 2048 blocks, NT=2
    deconv_mma<32, 16, 2, 16, 64, 64, true><<<2048, 256>>>(
        d1, dW2, db2, d2, SLOT(3));
    bn_stats<<<16 * 32, 256>>>(d2, 16, 128 * 128);
    bn_finalize<<<16, 32>>>(dg2, dbt2, 128 * 128, SLOT(4));

    // deconv3: 16->3, 128x128 in. KC=16. 8192 blocks, NT=1
    deconv_mma<16, 3, 1, 16, 128, 128, true><<<8192, 256>>>(
        d2, dW3, db3, out, SLOT(4));
    {
        const long long T = (long long)BB * 3 * 256 * 256;
        bn_stats<<<3 * 32, 256>>>(out, 3, 256 * 256);
        bn_finalize<<<3, 32>>>(dg3, dbt3, 256 * 256, SLOT(5));
        bn_apply_tanh<<<nblk(T / 4), 256>>>(out, 3, 256 * 256, (int)(T / 4), SLOT(5));
    }
    #undef SLOT
}